// round 11
// baseline (speedup 1.0000x reference)
#include <cuda_runtime.h>

// ============================================================================
// EquivariantSpatialConv: fused 3x3 replicate-pad depthwise spatial average
// + fully-connected CG tensor product (irreps 1x4e + 1x6e) + residual.
//
// R11: retile 32x3 / 96 threads, __launch_bounds__(96, 9) -> 27 warps/SM and
// 4.61 waves (vs 4.45@7CTA quantized to 5 -> ~11% tail idle). Reg budget
// unchanged (75->72), so no new spill pressure. TP stage identical to R10
// (CG immediates, symmetry folds, unweighted-z diagonal blocks).
// ============================================================================

#define DEVHOST __host__ __device__

// ---------------- compile-time scalar math ----------------
DEVHOST constexpr double cfact(int n) {
    double r = 1.0;
    for (int i = 2; i <= n; ++i) r *= (double)i;
    return r;
}

DEVHOST constexpr double csqrt(double x) {
    if (x <= 0.0) return 0.0;
    double g = x > 1.0 ? x : 1.0;
    for (int it = 0; it < 48; ++it) g = 0.5 * (g + x / g);
    return g;
}

struct CD { double re, im; };
DEVHOST constexpr CD cmul(CD a, CD b) {
    return CD{a.re * b.re - a.im * b.im, a.re * b.im + a.im * b.re};
}
DEVHOST constexpr CD cconj(CD a) { return CD{a.re, -a.im}; }

DEVHOST constexpr double su2_cg(int j1, int j2, int j3, int m1, int m2, int m3) {
    if (m3 != m1 + m2) return 0.0;
    if (m1 < -j1 || m1 > j1 || m2 < -j2 || m2 > j2 || m3 < -j3 || m3 > j3) return 0.0;
    double pref0 = (2.0 * j3 + 1.0) * cfact(j1 + j2 - j3) * cfact(j1 - j2 + j3) *
                   cfact(-j1 + j2 + j3) / cfact(j1 + j2 + j3 + 1);
    double pref = csqrt(pref0 * cfact(j3 + m3) * cfact(j3 - m3) * cfact(j1 - m1) *
                        cfact(j1 + m1) * cfact(j2 - m2) * cfact(j2 + m2));
    int kmin = 0;
    if (-(j3 - j2 + m1) > kmin) kmin = -(j3 - j2 + m1);
    if (-(j3 - j1 - m2) > kmin) kmin = -(j3 - j1 - m2);
    int kmax = j1 + j2 - j3;
    if (j1 - m1 < kmax) kmax = j1 - m1;
    if (j2 + m2 < kmax) kmax = j2 + m2;
    double s = 0.0;
    for (int k = kmin; k <= kmax; ++k) {
        double d = cfact(k) * cfact(j1 + j2 - j3 - k) * cfact(j1 - m1 - k) *
                   cfact(j2 + m2 - k) * cfact(j3 - j2 + m1 + k) * cfact(j3 - j1 - m2 + k);
        s += ((k & 1) ? -1.0 : 1.0) / d;
    }
    return pref * s;
}

DEVHOST constexpr CD qent(int l, int r, int c) {
    constexpr double S2 = 0.70710678118654752440;
    int m = r - l;
    CD v{0.0, 0.0};
    if (m < 0) {
        if (c == l - m)      v = CD{S2, 0.0};
        else if (c == l + m) v = CD{0.0, -S2};
    } else if (m == 0) {
        if (c == l) v = CD{1.0, 0.0};
    } else {
        double sg = (m & 1) ? -1.0 : 1.0;
        if (c == l + m)      v = CD{sg * S2, 0.0};
        else if (c == l - m) v = CD{0.0, sg * S2};
    }
    int ph = l & 3;
    CD f = (ph == 0) ? CD{1, 0} : (ph == 1) ? CD{0, -1} : (ph == 2) ? CD{-1, 0} : CD{0, 1};
    return cmul(v, f);
}

DEVHOST constexpr double real_cg_entry(int l1, int l2, int l3, int a, int b, int c) {
    int d1 = a >= l1 ? a - l1 : l1 - a;
    int d2 = b >= l2 ? b - l2 : l2 - b;
    int d3 = c >= l3 ? c - l3 : l3 - c;
    CD sum{0.0, 0.0};
    int ni = d1 ? 2 : 1;
    int nk = d2 ? 2 : 1;
    for (int si = 0; si < ni; ++si) {
        int i = d1 ? (si ? l1 + d1 : l1 - d1) : l1;
        int m1 = i - l1;
        CD q1 = qent(l1, i, a);
        for (int sk = 0; sk < nk; ++sk) {
            int k = d2 ? (sk ? l2 + d2 : l2 - d2) : l2;
            int m2 = k - l2;
            int m3 = m1 + m2;
            if (m3 < -l3 || m3 > l3) continue;
            int am3 = m3 < 0 ? -m3 : m3;
            if (am3 != d3) continue;
            int n = l3 + m3;
            CD q2 = qent(l2, k, b);
            CD q3 = cconj(qent(l3, c, n));
            double C = su2_cg(l1, l2, l3, m1, m2, m3);
            CD t = cmul(cmul(q1, q2), q3);
            sum.re += t.re * C;
            sum.im += t.im * C;
        }
    }
    return sum.re;
}

template <int L1, int L2, int L3>
struct CGT {
    float v[2 * L1 + 1][2 * L2 + 1][2 * L3 + 1];
};

template <int L1, int L2, int L3>
DEVHOST constexpr CGT<L1, L2, L3> make_cg() {
    double tmp[2 * L1 + 1][2 * L2 + 1][2 * L3 + 1] = {};
    double ss = 0.0;
    for (int a = 0; a < 2 * L1 + 1; ++a)
        for (int b = 0; b < 2 * L2 + 1; ++b)
            for (int c = 0; c < 2 * L3 + 1; ++c) {
                double e = real_cg_entry(L1, L2, L3, a, b, c);
                tmp[a][b][c] = e;
                ss += e * e;
            }
    double inv = 1.0 / csqrt(ss);
    CGT<L1, L2, L3> r{};
    for (int a = 0; a < 2 * L1 + 1; ++a)
        for (int b = 0; b < 2 * L2 + 1; ++b)
            for (int c = 0; c < 2 * L3 + 1; ++c)
                r.v[a][b][c] = (float)(tmp[a][b][c] * inv);
    return r;
}

// Namespace-scope constexpr CG tensors (static storage: usable in constant
// expressions from any lambda depth inside function templates).
template <int L1, int L2, int L3>
inline constexpr CGT<L1, L2, L3> CG = make_cg<L1, L2, L3>();

// ---------------- compile-time unrolling helpers ----------------
template <int V> struct IC { static constexpr int value = V; };

template <int N, int I = 0, class F>
__device__ __forceinline__ void sfor(F&& f) {
    if constexpr (I < N) {
        f(IC<I>{});
        sfor<N, I + 1>(static_cast<F&&>(f));
    }
}

template <class T>
DEVHOST constexpr bool rowany(const T& t, int a, int b, int dk) {
    for (int k = 0; k < dk; ++k)
        if (t.v[a][b][k] != 0.0f) return true;
    return false;
}
template <class T>
DEVHOST constexpr bool rowany2(const T& t, int a, int b, int dk) {
    for (int k = 0; k < dk; ++k)
        if (t.v[a][b][k] != 0.0f || t.v[b][a][k] != 0.0f) return true;
    return false;
}
template <class T>
DEVHOST constexpr bool symk(const T& t, int a, int b, int dk) {
    for (int k = 0; k < dk; ++k)
        if (t.v[a][b][k] != t.v[b][a][k]) return false;
    return true;
}
template <class TA, class TB>
DEVHOST constexpr bool eqk(const TA& A, int i, int j, const TB& B, int bi, int bj, int dk) {
    for (int k = 0; k < dk; ++k)
        if (A.v[i][j][k] != B.v[bi][bj][k]) return false;
    return true;
}

// ---------------- packed f32x2 helpers ----------------
__device__ __forceinline__ float2 f2fma(float2 a, float2 b, float2 c) {
    float2 d;
    asm("fma.rn.f32x2 %0, %1, %2, %3;"
        : "=l"(*reinterpret_cast<unsigned long long*>(&d))
        : "l"(*reinterpret_cast<unsigned long long*>(&a)),
          "l"(*reinterpret_cast<unsigned long long*>(&b)),
          "l"(*reinterpret_cast<unsigned long long*>(&c)));
    return d;
}
__device__ __forceinline__ float2 f2mul(float2 a, float2 b) {
    float2 d;
    asm("mul.rn.f32x2 %0, %1, %2;"
        : "=l"(*reinterpret_cast<unsigned long long*>(&d))
        : "l"(*reinterpret_cast<unsigned long long*>(&a)),
          "l"(*reinterpret_cast<unsigned long long*>(&b)));
    return d;
}

// ---------------- tensor-product blocks ----------------
// Diagonal block (L,L,*): UNWEIGHTED accumulation into z[22]
// (z[0..8] <- CG<L,L,4>, z[9..21] <- CG<L,L,6>); weights applied by caller.
template <int L, int O>
__device__ __forceinline__ void tp_diag_z(const float* __restrict__ x1,
                                          const float* __restrict__ x2,
                                          float* __restrict__ z) {
    constexpr int D = 2 * L + 1;
    sfor<D>([&](auto I) {
        constexpr int i = decltype(I)::value;
        sfor<D>([&](auto J) {
            constexpr int j = decltype(J)::value;
            if constexpr (j >= i) {
                constexpr bool l0 = rowany2(CG<L, L, 4>, i, j, 9);
                constexpr bool l1 = rowany2(CG<L, L, 6>, i, j, 13);
                if constexpr (l0 || l1) {
                    if constexpr (i == j) {
                        float p = x1[O + i] * x2[O + i];
                        sfor<9>([&](auto K) {
                            constexpr int k = decltype(K)::value;
                            constexpr float cv = CG<L, L, 4>.v[i][i][k];
                            if constexpr (cv != 0.0f) z[k] = __fmaf_rn(cv, p, z[k]);
                        });
                        sfor<13>([&](auto K) {
                            constexpr int k = decltype(K)::value;
                            constexpr float cv = CG<L, L, 6>.v[i][i][k];
                            if constexpr (cv != 0.0f) z[9 + k] = __fmaf_rn(cv, p, z[9 + k]);
                        });
                    } else if constexpr (symk(CG<L, L, 4>, i, j, 9) && symk(CG<L, L, 6>, i, j, 13)) {
                        float s = __fmaf_rn(x1[O + j], x2[O + i], x1[O + i] * x2[O + j]);
                        sfor<9>([&](auto K) {
                            constexpr int k = decltype(K)::value;
                            constexpr float cv = CG<L, L, 4>.v[i][j][k];
                            if constexpr (cv != 0.0f) z[k] = __fmaf_rn(cv, s, z[k]);
                        });
                        sfor<13>([&](auto K) {
                            constexpr int k = decltype(K)::value;
                            constexpr float cv = CG<L, L, 6>.v[i][j][k];
                            if constexpr (cv != 0.0f) z[9 + k] = __fmaf_rn(cv, s, z[9 + k]);
                        });
                    } else {
                        // fallback (not expected for even l1+l2+l3): both orders
                        float p1 = x1[O + i] * x2[O + j];
                        float p2 = x1[O + j] * x2[O + i];
                        sfor<9>([&](auto K) {
                            constexpr int k = decltype(K)::value;
                            constexpr float c1 = CG<L, L, 4>.v[i][j][k];
                            constexpr float c2 = CG<L, L, 4>.v[j][i][k];
                            if constexpr (c1 != 0.0f) z[k] = __fmaf_rn(c1, p1, z[k]);
                            if constexpr (c2 != 0.0f) z[k] = __fmaf_rn(c2, p2, z[k]);
                        });
                        sfor<13>([&](auto K) {
                            constexpr int k = decltype(K)::value;
                            constexpr float c1 = CG<L, L, 6>.v[i][j][k];
                            constexpr float c2 = CG<L, L, 6>.v[j][i][k];
                            if constexpr (c1 != 0.0f) z[9 + k] = __fmaf_rn(c1, p1, z[9 + k]);
                            if constexpr (c2 != 0.0f) z[9 + k] = __fmaf_rn(c2, p2, z[9 + k]);
                        });
                    }
                }
            }
        });
    });
}

// Cross block: paths (4,6,c) and (6,4,c), merged when the CG tensors
// coincide under exchange (verified at compile time). Weighted into acc.
__device__ __forceinline__ void tp_cross(const float* __restrict__ x1,
                                         const float* __restrict__ x2,
                                         float* __restrict__ acc,
                                         float wA0, float wA1, float wB0, float wB1) {
    sfor<9>([&](auto I) {
        constexpr int i = decltype(I)::value;
        sfor<13>([&](auto J) {
            constexpr int j = decltype(J)::value;
            constexpr bool a0 = rowany(CG<4, 6, 4>, i, j, 9);
            constexpr bool b0 = rowany(CG<6, 4, 4>, j, i, 9);
            constexpr bool a1 = rowany(CG<4, 6, 6>, i, j, 13);
            constexpr bool b1 = rowany(CG<6, 4, 6>, j, i, 13);
            if constexpr (a0 || b0 || a1 || b1) {
                float p1 = x1[i] * x2[9 + j];
                float p2 = x2[i] * x1[9 + j];
                if constexpr (a0 || b0) {
                    if constexpr (a0 && b0 && eqk(CG<4, 6, 4>, i, j, CG<6, 4, 4>, j, i, 9)) {
                        float u = __fmaf_rn(wB0, p2, p1 * wA0);
                        sfor<9>([&](auto K) {
                            constexpr int k = decltype(K)::value;
                            constexpr float cv = CG<4, 6, 4>.v[i][j][k];
                            if constexpr (cv != 0.0f) acc[k] = __fmaf_rn(cv, u, acc[k]);
                        });
                    } else {
                        if constexpr (a0) {
                            float t1 = p1 * wA0;
                            sfor<9>([&](auto K) {
                                constexpr int k = decltype(K)::value;
                                constexpr float cv = CG<4, 6, 4>.v[i][j][k];
                                if constexpr (cv != 0.0f) acc[k] = __fmaf_rn(cv, t1, acc[k]);
                            });
                        }
                        if constexpr (b0) {
                            float t2 = p2 * wB0;
                            sfor<9>([&](auto K) {
                                constexpr int k = decltype(K)::value;
                                constexpr float cv = CG<6, 4, 4>.v[j][i][k];
                                if constexpr (cv != 0.0f) acc[k] = __fmaf_rn(cv, t2, acc[k]);
                            });
                        }
                    }
                }
                if constexpr (a1 || b1) {
                    if constexpr (a1 && b1 && eqk(CG<4, 6, 6>, i, j, CG<6, 4, 6>, j, i, 13)) {
                        float u = __fmaf_rn(wB1, p2, p1 * wA1);
                        sfor<13>([&](auto K) {
                            constexpr int k = decltype(K)::value;
                            constexpr float cv = CG<4, 6, 6>.v[i][j][k];
                            if constexpr (cv != 0.0f) acc[9 + k] = __fmaf_rn(cv, u, acc[9 + k]);
                        });
                    } else {
                        if constexpr (a1) {
                            float t1 = p1 * wA1;
                            sfor<13>([&](auto K) {
                                constexpr int k = decltype(K)::value;
                                constexpr float cv = CG<4, 6, 6>.v[i][j][k];
                                if constexpr (cv != 0.0f) acc[9 + k] = __fmaf_rn(cv, t1, acc[9 + k]);
                            });
                        }
                        if constexpr (b1) {
                            float t2 = p2 * wB1;
                            sfor<13>([&](auto K) {
                                constexpr int k = decltype(K)::value;
                                constexpr float cv = CG<6, 4, 6>.v[j][i][k];
                                if constexpr (cv != 0.0f) acc[9 + k] = __fmaf_rn(cv, t2, acc[9 + k]);
                            });
                        }
                    }
                }
            }
        });
    });
}

// ---------------- kernel ----------------
constexpr int H = 768, W = 768;
constexpr int TX = 32, TY = 3;             // 96-thread tile
constexpr int NT = TX * TY;                // 96
constexpr int HTX = TX + 2, HTY = TY + 2;  // 34 x 5 haloed tile
constexpr int NPIX = HTX * HTY;            // 170

__global__ void __launch_bounds__(NT, 9) eq_spatial_tp_kernel(
    const float* __restrict__ f4, const float* __restrict__ f6,
    const float* __restrict__ sw, const float* __restrict__ wp,
    float* __restrict__ out4, float* __restrict__ out6) {
    // float4-group, pixel-major smem: groups 0-4 hold ch 4g..4g+3, group 5 ch 20-21.
    __shared__ float4 tile4[5][NPIX];   // 13600 B
    __shared__ float2 tile5[NPIX];      // 1360 B -> 14960 B total, 9 CTAs = 135 KB

    const int tid = threadIdx.x;
    const int bx = blockIdx.x, by = blockIdx.y;
    const int gx0 = bx * TX - 1, gy0 = by * TY - 1;

    // hoist weight loads so their latency overlaps the tile load
    float2 swp[9];
#pragma unroll
    for (int q = 0; q < 9; ++q) {
        float s = sw[q];
        swp[q] = make_float2(s, s);
    }
    float wcomb[8];
#pragma unroll
    for (int p = 0; p < 8; ++p) wcomb[p] = 0.5f * wp[p];  // ALPHA = 1/sqrt(4)

    // ---- pixel-outer haloed-tile load (<=2 pixels/thread, compile-time offsets) ----
#pragma unroll
    for (int pix = tid; pix < NPIX; pix += NT) {
        int r = pix / HTX, c = pix - r * HTX;
        int gy = gy0 + r; gy = gy < 0 ? 0 : (gy > H - 1 ? H - 1 : gy);
        int gx = gx0 + c; gx = gx < 0 ? 0 : (gx > W - 1 ? W - 1 : gx);
        int g = gy * W + gx;
        const float* p4 = f4 + g * 9;
        const float* p6 = f6 + g * 13;
        float v[22];
#pragma unroll
        for (int ch = 0; ch < 9; ++ch) v[ch] = p4[ch];
#pragma unroll
        for (int ch = 0; ch < 13; ++ch) v[9 + ch] = p6[ch];
#pragma unroll
        for (int gg = 0; gg < 5; ++gg)
            tile4[gg][pix] = make_float4(v[4 * gg], v[4 * gg + 1], v[4 * gg + 2], v[4 * gg + 3]);
        tile5[pix] = make_float2(v[20], v[21]);
    }
    __syncthreads();

    const int tx = tid & 31, ty = tid >> 5;

    // x1 = center features; x2 = weighted 3x3 neighbor average (packed f32x2)
    __align__(16) float x1[22];
    __align__(8) float x2[22];
    float2* x1v = reinterpret_cast<float2*>(x1);
    float2* x2v = reinterpret_cast<float2*>(x2);
    {
        const int cpix = (ty + 1) * HTX + (tx + 1);
#pragma unroll
        for (int gg = 0; gg < 5; ++gg) {
            float4 t = tile4[gg][cpix];
            x1v[2 * gg] = make_float2(t.x, t.y);
            x1v[2 * gg + 1] = make_float2(t.z, t.w);
        }
        x1v[10] = tile5[cpix];
#pragma unroll
        for (int p = 0; p < 11; ++p) x2v[p] = f2mul(swp[4], x1v[p]);
    }
#pragma unroll
    for (int dy = 0; dy < 3; ++dy)
#pragma unroll
        for (int dx = 0; dx < 3; ++dx) {
            if (dy == 1 && dx == 1) continue;
            const int npix = (ty + dy) * HTX + (tx + dx);
            const float2 wq = swp[dy * 3 + dx];
#pragma unroll
            for (int gg = 0; gg < 5; ++gg) {
                float4 t = tile4[gg][npix];
                x2v[2 * gg] = f2fma(wq, make_float2(t.x, t.y), x2v[2 * gg]);
                x2v[2 * gg + 1] = f2fma(wq, make_float2(t.z, t.w), x2v[2 * gg + 1]);
            }
            x2v[10] = f2fma(wq, tile5[npix], x2v[10]);
        }

    // ---- TP, ordered for register liveness ----
    float acc[22];
    {
        // diag44 unweighted -> z; acc born as x1 + w*z (z dies into acc)
        float z[22];
#pragma unroll
        for (int k = 0; k < 22; ++k) z[k] = 0.0f;
        tp_diag_z<4, 0>(x1, x2, z);
#pragma unroll
        for (int k = 0; k < 9; ++k) acc[k] = __fmaf_rn(wcomb[0], z[k], x1[k]);
#pragma unroll
        for (int k = 0; k < 13; ++k) acc[9 + k] = __fmaf_rn(wcomb[1], z[9 + k], x1[9 + k]);
    }

    // cross block (merged), weighted into acc
    tp_cross(x1, x2, acc, wcomb[2], wcomb[3], wcomb[4], wcomb[5]);

    {
        // diag66 unweighted -> z (x1[0..8]/x2[0..8] dead by now)
        float z[22];
#pragma unroll
        for (int k = 0; k < 22; ++k) z[k] = 0.0f;
        tp_diag_z<6, 9>(x1, x2, z);
#pragma unroll
        for (int k = 0; k < 9; ++k) acc[k] = __fmaf_rn(wcomb[6], z[k], acc[k]);
#pragma unroll
        for (int k = 0; k < 13; ++k) acc[9 + k] = __fmaf_rn(wcomb[7], z[9 + k], acc[9 + k]);
    }

    // store (output layout: flat [N*9] then [N*13])
    const int gy = by * TY + ty, gx = bx * TX + tx;
    const int g = gy * W + gx;
#pragma unroll
    for (int k = 0; k < 9; ++k) out4[g * 9 + k] = acc[k];
#pragma unroll
    for (int k = 0; k < 13; ++k) out6[g * 13 + k] = acc[9 + k];
}

extern "C" void kernel_launch(void* const* d_in, const int* in_sizes, int n_in,
                              void* d_out, int out_size) {
    const float* f4 = (const float*)d_in[0];
    const float* f6 = (const float*)d_in[1];
    const float* sw = (const float*)d_in[2];  // spatial_weights [3,3]
    const float* wp = (const float*)d_in[3];  // w_paths [8]
    float* out = (float*)d_out;
    const size_t N = (size_t)H * W;

    dim3 grid(W / TX, H / TY);  // 24 x 256
    eq_spatial_tp_kernel<<<grid, NT>>>(f4, f6, sw, wp, out, out + N * 9);
}

// round 12
// speedup vs baseline: 1.0337x; 1.0337x over previous
#include <cuda_runtime.h>

// ============================================================================
// EquivariantSpatialConv: fused 3x3 replicate-pad depthwise spatial average
// + fully-connected CG tensor product (irreps 1x4e + 1x6e) + residual.
//
// R12: R10 per-tile pipeline (128-thr CTAs, 7/SM, 32x4 tile, LDG->STS load,
// float4 smem, f32x2 spatial, unweighted-z TP) wrapped in a persistent-lite
// tile-stride loop over 1036 CTAs (= 148 SMs x 7). Kills the 5th-wave
// quantization tail (4.45 waves -> tail of ONE tile). 128 threads = 4 warps
// keeps all 4 SMSPs fed (R11's 96-thr CTA starved SMSP 3).
// ============================================================================

#define DEVHOST __host__ __device__

// ---------------- compile-time scalar math ----------------
DEVHOST constexpr double cfact(int n) {
    double r = 1.0;
    for (int i = 2; i <= n; ++i) r *= (double)i;
    return r;
}

DEVHOST constexpr double csqrt(double x) {
    if (x <= 0.0) return 0.0;
    double g = x > 1.0 ? x : 1.0;
    for (int it = 0; it < 48; ++it) g = 0.5 * (g + x / g);
    return g;
}

struct CD { double re, im; };
DEVHOST constexpr CD cmul(CD a, CD b) {
    return CD{a.re * b.re - a.im * b.im, a.re * b.im + a.im * b.re};
}
DEVHOST constexpr CD cconj(CD a) { return CD{a.re, -a.im}; }

DEVHOST constexpr double su2_cg(int j1, int j2, int j3, int m1, int m2, int m3) {
    if (m3 != m1 + m2) return 0.0;
    if (m1 < -j1 || m1 > j1 || m2 < -j2 || m2 > j2 || m3 < -j3 || m3 > j3) return 0.0;
    double pref0 = (2.0 * j3 + 1.0) * cfact(j1 + j2 - j3) * cfact(j1 - j2 + j3) *
                   cfact(-j1 + j2 + j3) / cfact(j1 + j2 + j3 + 1);
    double pref = csqrt(pref0 * cfact(j3 + m3) * cfact(j3 - m3) * cfact(j1 - m1) *
                        cfact(j1 + m1) * cfact(j2 - m2) * cfact(j2 + m2));
    int kmin = 0;
    if (-(j3 - j2 + m1) > kmin) kmin = -(j3 - j2 + m1);
    if (-(j3 - j1 - m2) > kmin) kmin = -(j3 - j1 - m2);
    int kmax = j1 + j2 - j3;
    if (j1 - m1 < kmax) kmax = j1 - m1;
    if (j2 + m2 < kmax) kmax = j2 + m2;
    double s = 0.0;
    for (int k = kmin; k <= kmax; ++k) {
        double d = cfact(k) * cfact(j1 + j2 - j3 - k) * cfact(j1 - m1 - k) *
                   cfact(j2 + m2 - k) * cfact(j3 - j2 + m1 + k) * cfact(j3 - j1 - m2 + k);
        s += ((k & 1) ? -1.0 : 1.0) / d;
    }
    return pref * s;
}

DEVHOST constexpr CD qent(int l, int r, int c) {
    constexpr double S2 = 0.70710678118654752440;
    int m = r - l;
    CD v{0.0, 0.0};
    if (m < 0) {
        if (c == l - m)      v = CD{S2, 0.0};
        else if (c == l + m) v = CD{0.0, -S2};
    } else if (m == 0) {
        if (c == l) v = CD{1.0, 0.0};
    } else {
        double sg = (m & 1) ? -1.0 : 1.0;
        if (c == l + m)      v = CD{sg * S2, 0.0};
        else if (c == l - m) v = CD{0.0, sg * S2};
    }
    int ph = l & 3;
    CD f = (ph == 0) ? CD{1, 0} : (ph == 1) ? CD{0, -1} : (ph == 2) ? CD{-1, 0} : CD{0, 1};
    return cmul(v, f);
}

DEVHOST constexpr double real_cg_entry(int l1, int l2, int l3, int a, int b, int c) {
    int d1 = a >= l1 ? a - l1 : l1 - a;
    int d2 = b >= l2 ? b - l2 : l2 - b;
    int d3 = c >= l3 ? c - l3 : l3 - c;
    CD sum{0.0, 0.0};
    int ni = d1 ? 2 : 1;
    int nk = d2 ? 2 : 1;
    for (int si = 0; si < ni; ++si) {
        int i = d1 ? (si ? l1 + d1 : l1 - d1) : l1;
        int m1 = i - l1;
        CD q1 = qent(l1, i, a);
        for (int sk = 0; sk < nk; ++sk) {
            int k = d2 ? (sk ? l2 + d2 : l2 - d2) : l2;
            int m2 = k - l2;
            int m3 = m1 + m2;
            if (m3 < -l3 || m3 > l3) continue;
            int am3 = m3 < 0 ? -m3 : m3;
            if (am3 != d3) continue;
            int n = l3 + m3;
            CD q2 = qent(l2, k, b);
            CD q3 = cconj(qent(l3, c, n));
            double C = su2_cg(l1, l2, l3, m1, m2, m3);
            CD t = cmul(cmul(q1, q2), q3);
            sum.re += t.re * C;
            sum.im += t.im * C;
        }
    }
    return sum.re;
}

template <int L1, int L2, int L3>
struct CGT {
    float v[2 * L1 + 1][2 * L2 + 1][2 * L3 + 1];
};

template <int L1, int L2, int L3>
DEVHOST constexpr CGT<L1, L2, L3> make_cg() {
    double tmp[2 * L1 + 1][2 * L2 + 1][2 * L3 + 1] = {};
    double ss = 0.0;
    for (int a = 0; a < 2 * L1 + 1; ++a)
        for (int b = 0; b < 2 * L2 + 1; ++b)
            for (int c = 0; c < 2 * L3 + 1; ++c) {
                double e = real_cg_entry(L1, L2, L3, a, b, c);
                tmp[a][b][c] = e;
                ss += e * e;
            }
    double inv = 1.0 / csqrt(ss);
    CGT<L1, L2, L3> r{};
    for (int a = 0; a < 2 * L1 + 1; ++a)
        for (int b = 0; b < 2 * L2 + 1; ++b)
            for (int c = 0; c < 2 * L3 + 1; ++c)
                r.v[a][b][c] = (float)(tmp[a][b][c] * inv);
    return r;
}

// Namespace-scope constexpr CG tensors (static storage: usable in constant
// expressions from any lambda depth inside function templates).
template <int L1, int L2, int L3>
inline constexpr CGT<L1, L2, L3> CG = make_cg<L1, L2, L3>();

// ---------------- compile-time unrolling helpers ----------------
template <int V> struct IC { static constexpr int value = V; };

template <int N, int I = 0, class F>
__device__ __forceinline__ void sfor(F&& f) {
    if constexpr (I < N) {
        f(IC<I>{});
        sfor<N, I + 1>(static_cast<F&&>(f));
    }
}

template <class T>
DEVHOST constexpr bool rowany(const T& t, int a, int b, int dk) {
    for (int k = 0; k < dk; ++k)
        if (t.v[a][b][k] != 0.0f) return true;
    return false;
}
template <class T>
DEVHOST constexpr bool rowany2(const T& t, int a, int b, int dk) {
    for (int k = 0; k < dk; ++k)
        if (t.v[a][b][k] != 0.0f || t.v[b][a][k] != 0.0f) return true;
    return false;
}
template <class T>
DEVHOST constexpr bool symk(const T& t, int a, int b, int dk) {
    for (int k = 0; k < dk; ++k)
        if (t.v[a][b][k] != t.v[b][a][k]) return false;
    return true;
}
template <class TA, class TB>
DEVHOST constexpr bool eqk(const TA& A, int i, int j, const TB& B, int bi, int bj, int dk) {
    for (int k = 0; k < dk; ++k)
        if (A.v[i][j][k] != B.v[bi][bj][k]) return false;
    return true;
}

// ---------------- packed f32x2 helpers ----------------
__device__ __forceinline__ float2 f2fma(float2 a, float2 b, float2 c) {
    float2 d;
    asm("fma.rn.f32x2 %0, %1, %2, %3;"
        : "=l"(*reinterpret_cast<unsigned long long*>(&d))
        : "l"(*reinterpret_cast<unsigned long long*>(&a)),
          "l"(*reinterpret_cast<unsigned long long*>(&b)),
          "l"(*reinterpret_cast<unsigned long long*>(&c)));
    return d;
}
__device__ __forceinline__ float2 f2mul(float2 a, float2 b) {
    float2 d;
    asm("mul.rn.f32x2 %0, %1, %2;"
        : "=l"(*reinterpret_cast<unsigned long long*>(&d))
        : "l"(*reinterpret_cast<unsigned long long*>(&a)),
          "l"(*reinterpret_cast<unsigned long long*>(&b)));
    return d;
}

// ---------------- tensor-product blocks ----------------
// Diagonal block (L,L,*): UNWEIGHTED accumulation into z[22]
// (z[0..8] <- CG<L,L,4>, z[9..21] <- CG<L,L,6>); weights applied by caller.
template <int L, int O>
__device__ __forceinline__ void tp_diag_z(const float* __restrict__ x1,
                                          const float* __restrict__ x2,
                                          float* __restrict__ z) {
    constexpr int D = 2 * L + 1;
    sfor<D>([&](auto I) {
        constexpr int i = decltype(I)::value;
        sfor<D>([&](auto J) {
            constexpr int j = decltype(J)::value;
            if constexpr (j >= i) {
                constexpr bool l0 = rowany2(CG<L, L, 4>, i, j, 9);
                constexpr bool l1 = rowany2(CG<L, L, 6>, i, j, 13);
                if constexpr (l0 || l1) {
                    if constexpr (i == j) {
                        float p = x1[O + i] * x2[O + i];
                        sfor<9>([&](auto K) {
                            constexpr int k = decltype(K)::value;
                            constexpr float cv = CG<L, L, 4>.v[i][i][k];
                            if constexpr (cv != 0.0f) z[k] = __fmaf_rn(cv, p, z[k]);
                        });
                        sfor<13>([&](auto K) {
                            constexpr int k = decltype(K)::value;
                            constexpr float cv = CG<L, L, 6>.v[i][i][k];
                            if constexpr (cv != 0.0f) z[9 + k] = __fmaf_rn(cv, p, z[9 + k]);
                        });
                    } else if constexpr (symk(CG<L, L, 4>, i, j, 9) && symk(CG<L, L, 6>, i, j, 13)) {
                        float s = __fmaf_rn(x1[O + j], x2[O + i], x1[O + i] * x2[O + j]);
                        sfor<9>([&](auto K) {
                            constexpr int k = decltype(K)::value;
                            constexpr float cv = CG<L, L, 4>.v[i][j][k];
                            if constexpr (cv != 0.0f) z[k] = __fmaf_rn(cv, s, z[k]);
                        });
                        sfor<13>([&](auto K) {
                            constexpr int k = decltype(K)::value;
                            constexpr float cv = CG<L, L, 6>.v[i][j][k];
                            if constexpr (cv != 0.0f) z[9 + k] = __fmaf_rn(cv, s, z[9 + k]);
                        });
                    } else {
                        // fallback (not expected for even l1+l2+l3): both orders
                        float p1 = x1[O + i] * x2[O + j];
                        float p2 = x1[O + j] * x2[O + i];
                        sfor<9>([&](auto K) {
                            constexpr int k = decltype(K)::value;
                            constexpr float c1 = CG<L, L, 4>.v[i][j][k];
                            constexpr float c2 = CG<L, L, 4>.v[j][i][k];
                            if constexpr (c1 != 0.0f) z[k] = __fmaf_rn(c1, p1, z[k]);
                            if constexpr (c2 != 0.0f) z[k] = __fmaf_rn(c2, p2, z[k]);
                        });
                        sfor<13>([&](auto K) {
                            constexpr int k = decltype(K)::value;
                            constexpr float c1 = CG<L, L, 6>.v[i][j][k];
                            constexpr float c2 = CG<L, L, 6>.v[j][i][k];
                            if constexpr (c1 != 0.0f) z[9 + k] = __fmaf_rn(c1, p1, z[9 + k]);
                            if constexpr (c2 != 0.0f) z[9 + k] = __fmaf_rn(c2, p2, z[9 + k]);
                        });
                    }
                }
            }
        });
    });
}

// Cross block: paths (4,6,c) and (6,4,c), merged when the CG tensors
// coincide under exchange (verified at compile time). Weighted into acc.
__device__ __forceinline__ void tp_cross(const float* __restrict__ x1,
                                         const float* __restrict__ x2,
                                         float* __restrict__ acc,
                                         float wA0, float wA1, float wB0, float wB1) {
    sfor<9>([&](auto I) {
        constexpr int i = decltype(I)::value;
        sfor<13>([&](auto J) {
            constexpr int j = decltype(J)::value;
            constexpr bool a0 = rowany(CG<4, 6, 4>, i, j, 9);
            constexpr bool b0 = rowany(CG<6, 4, 4>, j, i, 9);
            constexpr bool a1 = rowany(CG<4, 6, 6>, i, j, 13);
            constexpr bool b1 = rowany(CG<6, 4, 6>, j, i, 13);
            if constexpr (a0 || b0 || a1 || b1) {
                float p1 = x1[i] * x2[9 + j];
                float p2 = x2[i] * x1[9 + j];
                if constexpr (a0 || b0) {
                    if constexpr (a0 && b0 && eqk(CG<4, 6, 4>, i, j, CG<6, 4, 4>, j, i, 9)) {
                        float u = __fmaf_rn(wB0, p2, p1 * wA0);
                        sfor<9>([&](auto K) {
                            constexpr int k = decltype(K)::value;
                            constexpr float cv = CG<4, 6, 4>.v[i][j][k];
                            if constexpr (cv != 0.0f) acc[k] = __fmaf_rn(cv, u, acc[k]);
                        });
                    } else {
                        if constexpr (a0) {
                            float t1 = p1 * wA0;
                            sfor<9>([&](auto K) {
                                constexpr int k = decltype(K)::value;
                                constexpr float cv = CG<4, 6, 4>.v[i][j][k];
                                if constexpr (cv != 0.0f) acc[k] = __fmaf_rn(cv, t1, acc[k]);
                            });
                        }
                        if constexpr (b0) {
                            float t2 = p2 * wB0;
                            sfor<9>([&](auto K) {
                                constexpr int k = decltype(K)::value;
                                constexpr float cv = CG<6, 4, 4>.v[j][i][k];
                                if constexpr (cv != 0.0f) acc[k] = __fmaf_rn(cv, t2, acc[k]);
                            });
                        }
                    }
                }
                if constexpr (a1 || b1) {
                    if constexpr (a1 && b1 && eqk(CG<4, 6, 6>, i, j, CG<6, 4, 6>, j, i, 13)) {
                        float u = __fmaf_rn(wB1, p2, p1 * wA1);
                        sfor<13>([&](auto K) {
                            constexpr int k = decltype(K)::value;
                            constexpr float cv = CG<4, 6, 6>.v[i][j][k];
                            if constexpr (cv != 0.0f) acc[9 + k] = __fmaf_rn(cv, u, acc[9 + k]);
                        });
                    } else {
                        if constexpr (a1) {
                            float t1 = p1 * wA1;
                            sfor<13>([&](auto K) {
                                constexpr int k = decltype(K)::value;
                                constexpr float cv = CG<4, 6, 6>.v[i][j][k];
                                if constexpr (cv != 0.0f) acc[9 + k] = __fmaf_rn(cv, t1, acc[9 + k]);
                            });
                        }
                        if constexpr (b1) {
                            float t2 = p2 * wB1;
                            sfor<13>([&](auto K) {
                                constexpr int k = decltype(K)::value;
                                constexpr float cv = CG<6, 4, 6>.v[j][i][k];
                                if constexpr (cv != 0.0f) acc[9 + k] = __fmaf_rn(cv, t2, acc[9 + k]);
                            });
                        }
                    }
                }
            }
        });
    });
}

// ---------------- kernel ----------------
constexpr int H = 768, W = 768;
constexpr int TX = 32, TY = 4;             // 128-thread tile
constexpr int NT = TX * TY;                // 128
constexpr int HTX = TX + 2, HTY = TY + 2;  // 34 x 6 haloed tile
constexpr int NPIX = HTX * HTY;            // 204
constexpr int TILES_X = W / TX;            // 24
constexpr int NTILES = (W / TX) * (H / TY);  // 4608
constexpr int NCTA = 148 * 7;              // 1036 = full residency, tile-stride loop

__global__ void __launch_bounds__(NT, 7) eq_spatial_tp_kernel(
    const float* __restrict__ f4, const float* __restrict__ f6,
    const float* __restrict__ sw, const float* __restrict__ wp,
    float* __restrict__ out4, float* __restrict__ out6) {
    // float4-group, pixel-major smem: groups 0-4 hold ch 4g..4g+3, group 5 ch 20-21.
    __shared__ float4 tile4[5][NPIX];   // 16320 B
    __shared__ float2 tile5[NPIX];      // 1632 B -> 17952 B total, 7 CTAs = 126 KB

    const int tid = threadIdx.x;
    const int tx = tid & 31, ty = tid >> 5;

    // weights loaded once per CTA (persistent-lite)
    float2 swp[9];
#pragma unroll
    for (int q = 0; q < 9; ++q) {
        float s = sw[q];
        swp[q] = make_float2(s, s);
    }
    float wcomb[8];
#pragma unroll
    for (int p = 0; p < 8; ++p) wcomb[p] = 0.5f * wp[p];  // ALPHA = 1/sqrt(4)

    for (int t = blockIdx.x; t < NTILES; t += NCTA) {
        const int by = t / TILES_X, bx = t - by * TILES_X;
        const int gx0 = bx * TX - 1, gy0 = by * TY - 1;

        // ---- pixel-outer haloed-tile load (2 pixels/thread, compile-time offsets) ----
#pragma unroll
        for (int pix = tid; pix < NPIX; pix += NT) {
            int r = pix / HTX, c = pix - r * HTX;
            int gy = gy0 + r; gy = gy < 0 ? 0 : (gy > H - 1 ? H - 1 : gy);
            int gx = gx0 + c; gx = gx < 0 ? 0 : (gx > W - 1 ? W - 1 : gx);
            int g = gy * W + gx;
            const float* p4 = f4 + g * 9;
            const float* p6 = f6 + g * 13;
            float v[22];
#pragma unroll
            for (int ch = 0; ch < 9; ++ch) v[ch] = p4[ch];
#pragma unroll
            for (int ch = 0; ch < 13; ++ch) v[9 + ch] = p6[ch];
#pragma unroll
            for (int gg = 0; gg < 5; ++gg)
                tile4[gg][pix] = make_float4(v[4 * gg], v[4 * gg + 1], v[4 * gg + 2], v[4 * gg + 3]);
            tile5[pix] = make_float2(v[20], v[21]);
        }
        __syncthreads();

        // x1 = center features; x2 = weighted 3x3 neighbor average (packed f32x2)
        __align__(16) float x1[22];
        __align__(8) float x2[22];
        float2* x1v = reinterpret_cast<float2*>(x1);
        float2* x2v = reinterpret_cast<float2*>(x2);
        {
            const int cpix = (ty + 1) * HTX + (tx + 1);
#pragma unroll
            for (int gg = 0; gg < 5; ++gg) {
                float4 tv = tile4[gg][cpix];
                x1v[2 * gg] = make_float2(tv.x, tv.y);
                x1v[2 * gg + 1] = make_float2(tv.z, tv.w);
            }
            x1v[10] = tile5[cpix];
#pragma unroll
            for (int p = 0; p < 11; ++p) x2v[p] = f2mul(swp[4], x1v[p]);
        }
#pragma unroll
        for (int dy = 0; dy < 3; ++dy)
#pragma unroll
            for (int dx = 0; dx < 3; ++dx) {
                if (dy == 1 && dx == 1) continue;
                const int npix = (ty + dy) * HTX + (tx + dx);
                const float2 wq = swp[dy * 3 + dx];
#pragma unroll
                for (int gg = 0; gg < 5; ++gg) {
                    float4 tv = tile4[gg][npix];
                    x2v[2 * gg] = f2fma(wq, make_float2(tv.x, tv.y), x2v[2 * gg]);
                    x2v[2 * gg + 1] = f2fma(wq, make_float2(tv.z, tv.w), x2v[2 * gg + 1]);
                }
                x2v[10] = f2fma(wq, tile5[npix], x2v[10]);
            }
        // all tile reads done; next iteration may overwrite smem after this
        __syncthreads();

        // ---- TP, ordered for register liveness ----
        float acc[22];
        {
            float z[22];
#pragma unroll
            for (int k = 0; k < 22; ++k) z[k] = 0.0f;
            tp_diag_z<4, 0>(x1, x2, z);
#pragma unroll
            for (int k = 0; k < 9; ++k) acc[k] = __fmaf_rn(wcomb[0], z[k], x1[k]);
#pragma unroll
            for (int k = 0; k < 13; ++k) acc[9 + k] = __fmaf_rn(wcomb[1], z[9 + k], x1[9 + k]);
        }

        tp_cross(x1, x2, acc, wcomb[2], wcomb[3], wcomb[4], wcomb[5]);

        {
            float z[22];
#pragma unroll
            for (int k = 0; k < 22; ++k) z[k] = 0.0f;
            tp_diag_z<6, 9>(x1, x2, z);
#pragma unroll
            for (int k = 0; k < 9; ++k) acc[k] = __fmaf_rn(wcomb[6], z[k], acc[k]);
#pragma unroll
            for (int k = 0; k < 13; ++k) acc[9 + k] = __fmaf_rn(wcomb[7], z[9 + k], acc[9 + k]);
        }

        // store (output layout: flat [N*9] then [N*13])
        const int gy = by * TY + ty, gx = bx * TX + tx;
        const int g = gy * W + gx;
#pragma unroll
        for (int k = 0; k < 9; ++k) out4[g * 9 + k] = acc[k];
#pragma unroll
        for (int k = 0; k < 13; ++k) out6[g * 13 + k] = acc[9 + k];
    }
}

extern "C" void kernel_launch(void* const* d_in, const int* in_sizes, int n_in,
                              void* d_out, int out_size) {
    const float* f4 = (const float*)d_in[0];
    const float* f6 = (const float*)d_in[1];
    const float* sw = (const float*)d_in[2];  // spatial_weights [3,3]
    const float* wp = (const float*)d_in[3];  // w_paths [8]
    float* out = (float*)d_out;
    const size_t N = (size_t)H * W;

    eq_spatial_tp_kernel<<<NCTA, NT>>>(f4, f6, sw, wp, out, out + N * 9);
}

// round 13
// speedup vs baseline: 1.2311x; 1.1909x over previous
#include <cuda_runtime.h>

// ============================================================================
// EquivariantSpatialConv: fused 3x3 replicate-pad depthwise spatial average
// + fully-connected CG tensor product (irreps 1x4e + 1x6e) + residual.
//
// R13: R10 structure (128-thr CTAs, 7/SM, single launch, pixel-outer load,
// float4 smem, f32x2 spatial, unweighted-z diagonals) + j-outer PRESCALED
// cross block: per-j A=w*x2[9+j], B=w*x1[9+j] turn each pair's 6 weight/
// product ops into 4 (u = fma(x2[i], B, x1[i]*A)), ~180 fewer ops/thread.
// ============================================================================

#define DEVHOST __host__ __device__

// ---------------- compile-time scalar math ----------------
DEVHOST constexpr double cfact(int n) {
    double r = 1.0;
    for (int i = 2; i <= n; ++i) r *= (double)i;
    return r;
}

DEVHOST constexpr double csqrt(double x) {
    if (x <= 0.0) return 0.0;
    double g = x > 1.0 ? x : 1.0;
    for (int it = 0; it < 48; ++it) g = 0.5 * (g + x / g);
    return g;
}

struct CD { double re, im; };
DEVHOST constexpr CD cmul(CD a, CD b) {
    return CD{a.re * b.re - a.im * b.im, a.re * b.im + a.im * b.re};
}
DEVHOST constexpr CD cconj(CD a) { return CD{a.re, -a.im}; }

DEVHOST constexpr double su2_cg(int j1, int j2, int j3, int m1, int m2, int m3) {
    if (m3 != m1 + m2) return 0.0;
    if (m1 < -j1 || m1 > j1 || m2 < -j2 || m2 > j2 || m3 < -j3 || m3 > j3) return 0.0;
    double pref0 = (2.0 * j3 + 1.0) * cfact(j1 + j2 - j3) * cfact(j1 - j2 + j3) *
                   cfact(-j1 + j2 + j3) / cfact(j1 + j2 + j3 + 1);
    double pref = csqrt(pref0 * cfact(j3 + m3) * cfact(j3 - m3) * cfact(j1 - m1) *
                        cfact(j1 + m1) * cfact(j2 - m2) * cfact(j2 + m2));
    int kmin = 0;
    if (-(j3 - j2 + m1) > kmin) kmin = -(j3 - j2 + m1);
    if (-(j3 - j1 - m2) > kmin) kmin = -(j3 - j1 - m2);
    int kmax = j1 + j2 - j3;
    if (j1 - m1 < kmax) kmax = j1 - m1;
    if (j2 + m2 < kmax) kmax = j2 + m2;
    double s = 0.0;
    for (int k = kmin; k <= kmax; ++k) {
        double d = cfact(k) * cfact(j1 + j2 - j3 - k) * cfact(j1 - m1 - k) *
                   cfact(j2 + m2 - k) * cfact(j3 - j2 + m1 + k) * cfact(j3 - j1 - m2 + k);
        s += ((k & 1) ? -1.0 : 1.0) / d;
    }
    return pref * s;
}

DEVHOST constexpr CD qent(int l, int r, int c) {
    constexpr double S2 = 0.70710678118654752440;
    int m = r - l;
    CD v{0.0, 0.0};
    if (m < 0) {
        if (c == l - m)      v = CD{S2, 0.0};
        else if (c == l + m) v = CD{0.0, -S2};
    } else if (m == 0) {
        if (c == l) v = CD{1.0, 0.0};
    } else {
        double sg = (m & 1) ? -1.0 : 1.0;
        if (c == l + m)      v = CD{sg * S2, 0.0};
        else if (c == l - m) v = CD{0.0, sg * S2};
    }
    int ph = l & 3;
    CD f = (ph == 0) ? CD{1, 0} : (ph == 1) ? CD{0, -1} : (ph == 2) ? CD{-1, 0} : CD{0, 1};
    return cmul(v, f);
}

DEVHOST constexpr double real_cg_entry(int l1, int l2, int l3, int a, int b, int c) {
    int d1 = a >= l1 ? a - l1 : l1 - a;
    int d2 = b >= l2 ? b - l2 : l2 - b;
    int d3 = c >= l3 ? c - l3 : l3 - c;
    CD sum{0.0, 0.0};
    int ni = d1 ? 2 : 1;
    int nk = d2 ? 2 : 1;
    for (int si = 0; si < ni; ++si) {
        int i = d1 ? (si ? l1 + d1 : l1 - d1) : l1;
        int m1 = i - l1;
        CD q1 = qent(l1, i, a);
        for (int sk = 0; sk < nk; ++sk) {
            int k = d2 ? (sk ? l2 + d2 : l2 - d2) : l2;
            int m2 = k - l2;
            int m3 = m1 + m2;
            if (m3 < -l3 || m3 > l3) continue;
            int am3 = m3 < 0 ? -m3 : m3;
            if (am3 != d3) continue;
            int n = l3 + m3;
            CD q2 = qent(l2, k, b);
            CD q3 = cconj(qent(l3, c, n));
            double C = su2_cg(l1, l2, l3, m1, m2, m3);
            CD t = cmul(cmul(q1, q2), q3);
            sum.re += t.re * C;
            sum.im += t.im * C;
        }
    }
    return sum.re;
}

template <int L1, int L2, int L3>
struct CGT {
    float v[2 * L1 + 1][2 * L2 + 1][2 * L3 + 1];
};

template <int L1, int L2, int L3>
DEVHOST constexpr CGT<L1, L2, L3> make_cg() {
    double tmp[2 * L1 + 1][2 * L2 + 1][2 * L3 + 1] = {};
    double ss = 0.0;
    for (int a = 0; a < 2 * L1 + 1; ++a)
        for (int b = 0; b < 2 * L2 + 1; ++b)
            for (int c = 0; c < 2 * L3 + 1; ++c) {
                double e = real_cg_entry(L1, L2, L3, a, b, c);
                tmp[a][b][c] = e;
                ss += e * e;
            }
    double inv = 1.0 / csqrt(ss);
    CGT<L1, L2, L3> r{};
    for (int a = 0; a < 2 * L1 + 1; ++a)
        for (int b = 0; b < 2 * L2 + 1; ++b)
            for (int c = 0; c < 2 * L3 + 1; ++c)
                r.v[a][b][c] = (float)(tmp[a][b][c] * inv);
    return r;
}

// Namespace-scope constexpr CG tensors (static storage: usable in constant
// expressions from any lambda depth inside function templates).
template <int L1, int L2, int L3>
inline constexpr CGT<L1, L2, L3> CG = make_cg<L1, L2, L3>();

// ---------------- compile-time unrolling helpers ----------------
template <int V> struct IC { static constexpr int value = V; };

template <int N, int I = 0, class F>
__device__ __forceinline__ void sfor(F&& f) {
    if constexpr (I < N) {
        f(IC<I>{});
        sfor<N, I + 1>(static_cast<F&&>(f));
    }
}

template <class T>
DEVHOST constexpr bool rowany(const T& t, int a, int b, int dk) {
    for (int k = 0; k < dk; ++k)
        if (t.v[a][b][k] != 0.0f) return true;
    return false;
}
template <class T>
DEVHOST constexpr bool rowany2(const T& t, int a, int b, int dk) {
    for (int k = 0; k < dk; ++k)
        if (t.v[a][b][k] != 0.0f || t.v[b][a][k] != 0.0f) return true;
    return false;
}
template <class T>
DEVHOST constexpr bool symk(const T& t, int a, int b, int dk) {
    for (int k = 0; k < dk; ++k)
        if (t.v[a][b][k] != t.v[b][a][k]) return false;
    return true;
}
template <class TA, class TB>
DEVHOST constexpr bool eqk(const TA& A, int i, int j, const TB& B, int bi, int bj, int dk) {
    for (int k = 0; k < dk; ++k)
        if (A.v[i][j][k] != B.v[bi][bj][k]) return false;
    return true;
}

// ---------------- packed f32x2 helpers ----------------
__device__ __forceinline__ float2 f2fma(float2 a, float2 b, float2 c) {
    float2 d;
    asm("fma.rn.f32x2 %0, %1, %2, %3;"
        : "=l"(*reinterpret_cast<unsigned long long*>(&d))
        : "l"(*reinterpret_cast<unsigned long long*>(&a)),
          "l"(*reinterpret_cast<unsigned long long*>(&b)),
          "l"(*reinterpret_cast<unsigned long long*>(&c)));
    return d;
}
__device__ __forceinline__ float2 f2mul(float2 a, float2 b) {
    float2 d;
    asm("mul.rn.f32x2 %0, %1, %2;"
        : "=l"(*reinterpret_cast<unsigned long long*>(&d))
        : "l"(*reinterpret_cast<unsigned long long*>(&a)),
          "l"(*reinterpret_cast<unsigned long long*>(&b)));
    return d;
}

// ---------------- tensor-product blocks ----------------
// Diagonal block (L,L,*): UNWEIGHTED accumulation into z[22]
// (z[0..8] <- CG<L,L,4>, z[9..21] <- CG<L,L,6>); weights applied by caller.
template <int L, int O>
__device__ __forceinline__ void tp_diag_z(const float* __restrict__ x1,
                                          const float* __restrict__ x2,
                                          float* __restrict__ z) {
    constexpr int D = 2 * L + 1;
    sfor<D>([&](auto I) {
        constexpr int i = decltype(I)::value;
        sfor<D>([&](auto J) {
            constexpr int j = decltype(J)::value;
            if constexpr (j >= i) {
                constexpr bool l0 = rowany2(CG<L, L, 4>, i, j, 9);
                constexpr bool l1 = rowany2(CG<L, L, 6>, i, j, 13);
                if constexpr (l0 || l1) {
                    if constexpr (i == j) {
                        float p = x1[O + i] * x2[O + i];
                        sfor<9>([&](auto K) {
                            constexpr int k = decltype(K)::value;
                            constexpr float cv = CG<L, L, 4>.v[i][i][k];
                            if constexpr (cv != 0.0f) z[k] = __fmaf_rn(cv, p, z[k]);
                        });
                        sfor<13>([&](auto K) {
                            constexpr int k = decltype(K)::value;
                            constexpr float cv = CG<L, L, 6>.v[i][i][k];
                            if constexpr (cv != 0.0f) z[9 + k] = __fmaf_rn(cv, p, z[9 + k]);
                        });
                    } else if constexpr (symk(CG<L, L, 4>, i, j, 9) && symk(CG<L, L, 6>, i, j, 13)) {
                        float s = __fmaf_rn(x1[O + j], x2[O + i], x1[O + i] * x2[O + j]);
                        sfor<9>([&](auto K) {
                            constexpr int k = decltype(K)::value;
                            constexpr float cv = CG<L, L, 4>.v[i][j][k];
                            if constexpr (cv != 0.0f) z[k] = __fmaf_rn(cv, s, z[k]);
                        });
                        sfor<13>([&](auto K) {
                            constexpr int k = decltype(K)::value;
                            constexpr float cv = CG<L, L, 6>.v[i][j][k];
                            if constexpr (cv != 0.0f) z[9 + k] = __fmaf_rn(cv, s, z[9 + k]);
                        });
                    } else {
                        // fallback (not expected for even l1+l2+l3): both orders
                        float p1 = x1[O + i] * x2[O + j];
                        float p2 = x1[O + j] * x2[O + i];
                        sfor<9>([&](auto K) {
                            constexpr int k = decltype(K)::value;
                            constexpr float c1 = CG<L, L, 4>.v[i][j][k];
                            constexpr float c2 = CG<L, L, 4>.v[j][i][k];
                            if constexpr (c1 != 0.0f) z[k] = __fmaf_rn(c1, p1, z[k]);
                            if constexpr (c2 != 0.0f) z[k] = __fmaf_rn(c2, p2, z[k]);
                        });
                        sfor<13>([&](auto K) {
                            constexpr int k = decltype(K)::value;
                            constexpr float c1 = CG<L, L, 6>.v[i][j][k];
                            constexpr float c2 = CG<L, L, 6>.v[j][i][k];
                            if constexpr (c1 != 0.0f) z[9 + k] = __fmaf_rn(c1, p1, z[9 + k]);
                            if constexpr (c2 != 0.0f) z[9 + k] = __fmaf_rn(c2, p2, z[9 + k]);
                        });
                    }
                }
            }
        });
    });
}

// Cross block with j-outer prescaling: for each j, A=w*x2[9+j] / B=w*x1[9+j]
// fold the path weights into per-j scalars; each (i,j) pair then costs
// u = fma(x2[i], B, x1[i]*A) per live output (2 ops instead of 3).
__device__ __forceinline__ void tp_cross(const float* __restrict__ x1,
                                         const float* __restrict__ x2,
                                         float* __restrict__ acc,
                                         float wA0, float wA1, float wB0, float wB1) {
    sfor<13>([&](auto J) {
        constexpr int j = decltype(J)::value;
        // per-j prescaled operands (transient registers)
        float A0 = wA0 * x2[9 + j];   // (4,6,4): x1[i] * A0
        float B0 = wB0 * x1[9 + j];   // (6,4,4): x2[i] * B0
        float A1 = wA1 * x2[9 + j];   // (4,6,6)
        float B1 = wB1 * x1[9 + j];   // (6,4,6)
        sfor<9>([&](auto I) {
            constexpr int i = decltype(I)::value;
            constexpr bool a0 = rowany(CG<4, 6, 4>, i, j, 9);
            constexpr bool b0 = rowany(CG<6, 4, 4>, j, i, 9);
            constexpr bool a1 = rowany(CG<4, 6, 6>, i, j, 13);
            constexpr bool b1 = rowany(CG<6, 4, 6>, j, i, 13);
            if constexpr (a0 || b0) {
                if constexpr (a0 && b0 && eqk(CG<4, 6, 4>, i, j, CG<6, 4, 4>, j, i, 9)) {
                    float u = __fmaf_rn(x2[i], B0, x1[i] * A0);
                    sfor<9>([&](auto K) {
                        constexpr int k = decltype(K)::value;
                        constexpr float cv = CG<4, 6, 4>.v[i][j][k];
                        if constexpr (cv != 0.0f) acc[k] = __fmaf_rn(cv, u, acc[k]);
                    });
                } else {
                    if constexpr (a0) {
                        float t1 = x1[i] * A0;
                        sfor<9>([&](auto K) {
                            constexpr int k = decltype(K)::value;
                            constexpr float cv = CG<4, 6, 4>.v[i][j][k];
                            if constexpr (cv != 0.0f) acc[k] = __fmaf_rn(cv, t1, acc[k]);
                        });
                    }
                    if constexpr (b0) {
                        float t2 = x2[i] * B0;
                        sfor<9>([&](auto K) {
                            constexpr int k = decltype(K)::value;
                            constexpr float cv = CG<6, 4, 4>.v[j][i][k];
                            if constexpr (cv != 0.0f) acc[k] = __fmaf_rn(cv, t2, acc[k]);
                        });
                    }
                }
            }
            if constexpr (a1 || b1) {
                if constexpr (a1 && b1 && eqk(CG<4, 6, 6>, i, j, CG<6, 4, 6>, j, i, 13)) {
                    float u = __fmaf_rn(x2[i], B1, x1[i] * A1);
                    sfor<13>([&](auto K) {
                        constexpr int k = decltype(K)::value;
                        constexpr float cv = CG<4, 6, 6>.v[i][j][k];
                        if constexpr (cv != 0.0f) acc[9 + k] = __fmaf_rn(cv, u, acc[9 + k]);
                    });
                } else {
                    if constexpr (a1) {
                        float t1 = x1[i] * A1;
                        sfor<13>([&](auto K) {
                            constexpr int k = decltype(K)::value;
                            constexpr float cv = CG<4, 6, 6>.v[i][j][k];
                            if constexpr (cv != 0.0f) acc[9 + k] = __fmaf_rn(cv, t1, acc[9 + k]);
                        });
                    }
                    if constexpr (b1) {
                        float t2 = x2[i] * B1;
                        sfor<13>([&](auto K) {
                            constexpr int k = decltype(K)::value;
                            constexpr float cv = CG<6, 4, 6>.v[j][i][k];
                            if constexpr (cv != 0.0f) acc[9 + k] = __fmaf_rn(cv, t2, acc[9 + k]);
                        });
                    }
                }
            }
        });
    });
}

// ---------------- kernel ----------------
constexpr int H = 768, W = 768;
constexpr int TX = 32, TY = 4;             // 128-thread tile
constexpr int NT = TX * TY;                // 128
constexpr int HTX = TX + 2, HTY = TY + 2;  // 34 x 6 haloed tile
constexpr int NPIX = HTX * HTY;            // 204

__global__ void __launch_bounds__(NT, 7) eq_spatial_tp_kernel(
    const float* __restrict__ f4, const float* __restrict__ f6,
    const float* __restrict__ sw, const float* __restrict__ wp,
    float* __restrict__ out4, float* __restrict__ out6) {
    // float4-group, pixel-major smem: groups 0-4 hold ch 4g..4g+3, group 5 ch 20-21.
    __shared__ float4 tile4[5][NPIX];   // 16320 B
    __shared__ float2 tile5[NPIX];      // 1632 B -> 17952 B total, 7 CTAs = 126 KB

    const int tid = threadIdx.x;
    const int bx = blockIdx.x, by = blockIdx.y;
    const int gx0 = bx * TX - 1, gy0 = by * TY - 1;

    // hoist weight loads so their latency overlaps the tile load
    float2 swp[9];
#pragma unroll
    for (int q = 0; q < 9; ++q) {
        float s = sw[q];
        swp[q] = make_float2(s, s);
    }
    float wcomb[8];
#pragma unroll
    for (int p = 0; p < 8; ++p) wcomb[p] = 0.5f * wp[p];  // ALPHA = 1/sqrt(4)

    // ---- pixel-outer haloed-tile load (2 pixels/thread, compile-time offsets) ----
#pragma unroll
    for (int pix = tid; pix < NPIX; pix += NT) {
        int r = pix / HTX, c = pix - r * HTX;
        int gy = gy0 + r; gy = gy < 0 ? 0 : (gy > H - 1 ? H - 1 : gy);
        int gx = gx0 + c; gx = gx < 0 ? 0 : (gx > W - 1 ? W - 1 : gx);
        int g = gy * W + gx;
        const float* p4 = f4 + g * 9;
        const float* p6 = f6 + g * 13;
        float v[22];
#pragma unroll
        for (int ch = 0; ch < 9; ++ch) v[ch] = p4[ch];
#pragma unroll
        for (int ch = 0; ch < 13; ++ch) v[9 + ch] = p6[ch];
#pragma unroll
        for (int gg = 0; gg < 5; ++gg)
            tile4[gg][pix] = make_float4(v[4 * gg], v[4 * gg + 1], v[4 * gg + 2], v[4 * gg + 3]);
        tile5[pix] = make_float2(v[20], v[21]);
    }
    __syncthreads();

    const int tx = tid & 31, ty = tid >> 5;

    // x1 = center features; x2 = weighted 3x3 neighbor average (packed f32x2)
    __align__(16) float x1[22];
    __align__(8) float x2[22];
    float2* x1v = reinterpret_cast<float2*>(x1);
    float2* x2v = reinterpret_cast<float2*>(x2);
    {
        const int cpix = (ty + 1) * HTX + (tx + 1);
#pragma unroll
        for (int gg = 0; gg < 5; ++gg) {
            float4 t = tile4[gg][cpix];
            x1v[2 * gg] = make_float2(t.x, t.y);
            x1v[2 * gg + 1] = make_float2(t.z, t.w);
        }
        x1v[10] = tile5[cpix];
#pragma unroll
        for (int p = 0; p < 11; ++p) x2v[p] = f2mul(swp[4], x1v[p]);
    }
#pragma unroll
    for (int dy = 0; dy < 3; ++dy)
#pragma unroll
        for (int dx = 0; dx < 3; ++dx) {
            if (dy == 1 && dx == 1) continue;
            const int npix = (ty + dy) * HTX + (tx + dx);
            const float2 wq = swp[dy * 3 + dx];
#pragma unroll
            for (int gg = 0; gg < 5; ++gg) {
                float4 t = tile4[gg][npix];
                x2v[2 * gg] = f2fma(wq, make_float2(t.x, t.y), x2v[2 * gg]);
                x2v[2 * gg + 1] = f2fma(wq, make_float2(t.z, t.w), x2v[2 * gg + 1]);
            }
            x2v[10] = f2fma(wq, tile5[npix], x2v[10]);
        }

    // ---- TP, ordered for register liveness ----
    float acc[22];
    {
        // diag44 unweighted -> z; acc born as x1 + w*z (z dies into acc)
        float z[22];
#pragma unroll
        for (int k = 0; k < 22; ++k) z[k] = 0.0f;
        tp_diag_z<4, 0>(x1, x2, z);
#pragma unroll
        for (int k = 0; k < 9; ++k) acc[k] = __fmaf_rn(wcomb[0], z[k], x1[k]);
#pragma unroll
        for (int k = 0; k < 13; ++k) acc[9 + k] = __fmaf_rn(wcomb[1], z[9 + k], x1[9 + k]);
    }

    // cross block (merged + j-prescaled), weighted into acc
    tp_cross(x1, x2, acc, wcomb[2], wcomb[3], wcomb[4], wcomb[5]);

    {
        // diag66 unweighted -> z (x1[0..8]/x2[0..8] dead by now)
        float z[22];
#pragma unroll
        for (int k = 0; k < 22; ++k) z[k] = 0.0f;
        tp_diag_z<6, 9>(x1, x2, z);
#pragma unroll
        for (int k = 0; k < 9; ++k) acc[k] = __fmaf_rn(wcomb[6], z[k], acc[k]);
#pragma unroll
        for (int k = 0; k < 13; ++k) acc[9 + k] = __fmaf_rn(wcomb[7], z[9 + k], acc[9 + k]);
    }

    // store (output layout: flat [N*9] then [N*13])
    const int gy = by * TY + ty, gx = bx * TX + tx;
    const int g = gy * W + gx;
#pragma unroll
    for (int k = 0; k < 9; ++k) out4[g * 9 + k] = acc[k];
#pragma unroll
    for (int k = 0; k < 13; ++k) out6[g * 13 + k] = acc[9 + k];
}

extern "C" void kernel_launch(void* const* d_in, const int* in_sizes, int n_in,
                              void* d_out, int out_size) {
    const float* f4 = (const float*)d_in[0];
    const float* f6 = (const float*)d_in[1];
    const float* sw = (const float*)d_in[2];  // spatial_weights [3,3]
    const float* wp = (const float*)d_in[3];  // w_paths [8]
    float* out = (float*)d_out;
    const size_t N = (size_t)H * W;

    dim3 grid(W / TX, H / TY);  // 24 x 192
    eq_spatial_tp_kernel<<<grid, NT>>>(f4, f6, sw, wp, out, out + N * 9);
}

// round 14
// speedup vs baseline: 1.2452x; 1.0115x over previous
#include <cuda_runtime.h>

// ============================================================================
// EquivariantSpatialConv: fused 3x3 replicate-pad depthwise spatial average
// + fully-connected CG tensor product (irreps 1x4e + 1x6e) + residual.
//
// R14: R13 (prescaled cross, unweighted-z diagonals, pixel-outer load,
// float4 smem, f32x2 spatial) + smem-staged coalesced stores: acc is staged
// into the dead tile smem (stride-23, conflict-free), then written as
// aligned STG.128 over contiguous per-row segments. Store L1 wavefronts
// drop ~198 -> ~25 per warp; arithmetic is bit-identical to R13.
// ============================================================================

#define DEVHOST __host__ __device__

// ---------------- compile-time scalar math ----------------
DEVHOST constexpr double cfact(int n) {
    double r = 1.0;
    for (int i = 2; i <= n; ++i) r *= (double)i;
    return r;
}

DEVHOST constexpr double csqrt(double x) {
    if (x <= 0.0) return 0.0;
    double g = x > 1.0 ? x : 1.0;
    for (int it = 0; it < 48; ++it) g = 0.5 * (g + x / g);
    return g;
}

struct CD { double re, im; };
DEVHOST constexpr CD cmul(CD a, CD b) {
    return CD{a.re * b.re - a.im * b.im, a.re * b.im + a.im * b.re};
}
DEVHOST constexpr CD cconj(CD a) { return CD{a.re, -a.im}; }

DEVHOST constexpr double su2_cg(int j1, int j2, int j3, int m1, int m2, int m3) {
    if (m3 != m1 + m2) return 0.0;
    if (m1 < -j1 || m1 > j1 || m2 < -j2 || m2 > j2 || m3 < -j3 || m3 > j3) return 0.0;
    double pref0 = (2.0 * j3 + 1.0) * cfact(j1 + j2 - j3) * cfact(j1 - j2 + j3) *
                   cfact(-j1 + j2 + j3) / cfact(j1 + j2 + j3 + 1);
    double pref = csqrt(pref0 * cfact(j3 + m3) * cfact(j3 - m3) * cfact(j1 - m1) *
                        cfact(j1 + m1) * cfact(j2 - m2) * cfact(j2 + m2));
    int kmin = 0;
    if (-(j3 - j2 + m1) > kmin) kmin = -(j3 - j2 + m1);
    if (-(j3 - j1 - m2) > kmin) kmin = -(j3 - j1 - m2);
    int kmax = j1 + j2 - j3;
    if (j1 - m1 < kmax) kmax = j1 - m1;
    if (j2 + m2 < kmax) kmax = j2 + m2;
    double s = 0.0;
    for (int k = kmin; k <= kmax; ++k) {
        double d = cfact(k) * cfact(j1 + j2 - j3 - k) * cfact(j1 - m1 - k) *
                   cfact(j2 + m2 - k) * cfact(j3 - j2 + m1 + k) * cfact(j3 - j1 - m2 + k);
        s += ((k & 1) ? -1.0 : 1.0) / d;
    }
    return pref * s;
}

DEVHOST constexpr CD qent(int l, int r, int c) {
    constexpr double S2 = 0.70710678118654752440;
    int m = r - l;
    CD v{0.0, 0.0};
    if (m < 0) {
        if (c == l - m)      v = CD{S2, 0.0};
        else if (c == l + m) v = CD{0.0, -S2};
    } else if (m == 0) {
        if (c == l) v = CD{1.0, 0.0};
    } else {
        double sg = (m & 1) ? -1.0 : 1.0;
        if (c == l + m)      v = CD{sg * S2, 0.0};
        else if (c == l - m) v = CD{0.0, sg * S2};
    }
    int ph = l & 3;
    CD f = (ph == 0) ? CD{1, 0} : (ph == 1) ? CD{0, -1} : (ph == 2) ? CD{-1, 0} : CD{0, 1};
    return cmul(v, f);
}

DEVHOST constexpr double real_cg_entry(int l1, int l2, int l3, int a, int b, int c) {
    int d1 = a >= l1 ? a - l1 : l1 - a;
    int d2 = b >= l2 ? b - l2 : l2 - b;
    int d3 = c >= l3 ? c - l3 : l3 - c;
    CD sum{0.0, 0.0};
    int ni = d1 ? 2 : 1;
    int nk = d2 ? 2 : 1;
    for (int si = 0; si < ni; ++si) {
        int i = d1 ? (si ? l1 + d1 : l1 - d1) : l1;
        int m1 = i - l1;
        CD q1 = qent(l1, i, a);
        for (int sk = 0; sk < nk; ++sk) {
            int k = d2 ? (sk ? l2 + d2 : l2 - d2) : l2;
            int m2 = k - l2;
            int m3 = m1 + m2;
            if (m3 < -l3 || m3 > l3) continue;
            int am3 = m3 < 0 ? -m3 : m3;
            if (am3 != d3) continue;
            int n = l3 + m3;
            CD q2 = qent(l2, k, b);
            CD q3 = cconj(qent(l3, c, n));
            double C = su2_cg(l1, l2, l3, m1, m2, m3);
            CD t = cmul(cmul(q1, q2), q3);
            sum.re += t.re * C;
            sum.im += t.im * C;
        }
    }
    return sum.re;
}

template <int L1, int L2, int L3>
struct CGT {
    float v[2 * L1 + 1][2 * L2 + 1][2 * L3 + 1];
};

template <int L1, int L2, int L3>
DEVHOST constexpr CGT<L1, L2, L3> make_cg() {
    double tmp[2 * L1 + 1][2 * L2 + 1][2 * L3 + 1] = {};
    double ss = 0.0;
    for (int a = 0; a < 2 * L1 + 1; ++a)
        for (int b = 0; b < 2 * L2 + 1; ++b)
            for (int c = 0; c < 2 * L3 + 1; ++c) {
                double e = real_cg_entry(L1, L2, L3, a, b, c);
                tmp[a][b][c] = e;
                ss += e * e;
            }
    double inv = 1.0 / csqrt(ss);
    CGT<L1, L2, L3> r{};
    for (int a = 0; a < 2 * L1 + 1; ++a)
        for (int b = 0; b < 2 * L2 + 1; ++b)
            for (int c = 0; c < 2 * L3 + 1; ++c)
                r.v[a][b][c] = (float)(tmp[a][b][c] * inv);
    return r;
}

// Namespace-scope constexpr CG tensors (static storage: usable in constant
// expressions from any lambda depth inside function templates).
template <int L1, int L2, int L3>
inline constexpr CGT<L1, L2, L3> CG = make_cg<L1, L2, L3>();

// ---------------- compile-time unrolling helpers ----------------
template <int V> struct IC { static constexpr int value = V; };

template <int N, int I = 0, class F>
__device__ __forceinline__ void sfor(F&& f) {
    if constexpr (I < N) {
        f(IC<I>{});
        sfor<N, I + 1>(static_cast<F&&>(f));
    }
}

template <class T>
DEVHOST constexpr bool rowany(const T& t, int a, int b, int dk) {
    for (int k = 0; k < dk; ++k)
        if (t.v[a][b][k] != 0.0f) return true;
    return false;
}
template <class T>
DEVHOST constexpr bool rowany2(const T& t, int a, int b, int dk) {
    for (int k = 0; k < dk; ++k)
        if (t.v[a][b][k] != 0.0f || t.v[b][a][k] != 0.0f) return true;
    return false;
}
template <class T>
DEVHOST constexpr bool symk(const T& t, int a, int b, int dk) {
    for (int k = 0; k < dk; ++k)
        if (t.v[a][b][k] != t.v[b][a][k]) return false;
    return true;
}
template <class TA, class TB>
DEVHOST constexpr bool eqk(const TA& A, int i, int j, const TB& B, int bi, int bj, int dk) {
    for (int k = 0; k < dk; ++k)
        if (A.v[i][j][k] != B.v[bi][bj][k]) return false;
    return true;
}

// ---------------- packed f32x2 helpers ----------------
__device__ __forceinline__ float2 f2fma(float2 a, float2 b, float2 c) {
    float2 d;
    asm("fma.rn.f32x2 %0, %1, %2, %3;"
        : "=l"(*reinterpret_cast<unsigned long long*>(&d))
        : "l"(*reinterpret_cast<unsigned long long*>(&a)),
          "l"(*reinterpret_cast<unsigned long long*>(&b)),
          "l"(*reinterpret_cast<unsigned long long*>(&c)));
    return d;
}
__device__ __forceinline__ float2 f2mul(float2 a, float2 b) {
    float2 d;
    asm("mul.rn.f32x2 %0, %1, %2;"
        : "=l"(*reinterpret_cast<unsigned long long*>(&d))
        : "l"(*reinterpret_cast<unsigned long long*>(&a)),
          "l"(*reinterpret_cast<unsigned long long*>(&b)));
    return d;
}

// ---------------- tensor-product blocks ----------------
// Diagonal block (L,L,*): UNWEIGHTED accumulation into z[22]
// (z[0..8] <- CG<L,L,4>, z[9..21] <- CG<L,L,6>); weights applied by caller.
template <int L, int O>
__device__ __forceinline__ void tp_diag_z(const float* __restrict__ x1,
                                          const float* __restrict__ x2,
                                          float* __restrict__ z) {
    constexpr int D = 2 * L + 1;
    sfor<D>([&](auto I) {
        constexpr int i = decltype(I)::value;
        sfor<D>([&](auto J) {
            constexpr int j = decltype(J)::value;
            if constexpr (j >= i) {
                constexpr bool l0 = rowany2(CG<L, L, 4>, i, j, 9);
                constexpr bool l1 = rowany2(CG<L, L, 6>, i, j, 13);
                if constexpr (l0 || l1) {
                    if constexpr (i == j) {
                        float p = x1[O + i] * x2[O + i];
                        sfor<9>([&](auto K) {
                            constexpr int k = decltype(K)::value;
                            constexpr float cv = CG<L, L, 4>.v[i][i][k];
                            if constexpr (cv != 0.0f) z[k] = __fmaf_rn(cv, p, z[k]);
                        });
                        sfor<13>([&](auto K) {
                            constexpr int k = decltype(K)::value;
                            constexpr float cv = CG<L, L, 6>.v[i][i][k];
                            if constexpr (cv != 0.0f) z[9 + k] = __fmaf_rn(cv, p, z[9 + k]);
                        });
                    } else if constexpr (symk(CG<L, L, 4>, i, j, 9) && symk(CG<L, L, 6>, i, j, 13)) {
                        float s = __fmaf_rn(x1[O + j], x2[O + i], x1[O + i] * x2[O + j]);
                        sfor<9>([&](auto K) {
                            constexpr int k = decltype(K)::value;
                            constexpr float cv = CG<L, L, 4>.v[i][j][k];
                            if constexpr (cv != 0.0f) z[k] = __fmaf_rn(cv, s, z[k]);
                        });
                        sfor<13>([&](auto K) {
                            constexpr int k = decltype(K)::value;
                            constexpr float cv = CG<L, L, 6>.v[i][j][k];
                            if constexpr (cv != 0.0f) z[9 + k] = __fmaf_rn(cv, s, z[9 + k]);
                        });
                    } else {
                        // fallback (not expected for even l1+l2+l3): both orders
                        float p1 = x1[O + i] * x2[O + j];
                        float p2 = x1[O + j] * x2[O + i];
                        sfor<9>([&](auto K) {
                            constexpr int k = decltype(K)::value;
                            constexpr float c1 = CG<L, L, 4>.v[i][j][k];
                            constexpr float c2 = CG<L, L, 4>.v[j][i][k];
                            if constexpr (c1 != 0.0f) z[k] = __fmaf_rn(c1, p1, z[k]);
                            if constexpr (c2 != 0.0f) z[k] = __fmaf_rn(c2, p2, z[k]);
                        });
                        sfor<13>([&](auto K) {
                            constexpr int k = decltype(K)::value;
                            constexpr float c1 = CG<L, L, 6>.v[i][j][k];
                            constexpr float c2 = CG<L, L, 6>.v[j][i][k];
                            if constexpr (c1 != 0.0f) z[9 + k] = __fmaf_rn(c1, p1, z[9 + k]);
                            if constexpr (c2 != 0.0f) z[9 + k] = __fmaf_rn(c2, p2, z[9 + k]);
                        });
                    }
                }
            }
        });
    });
}

// Cross block with j-outer prescaling: for each j, A=w*x2[9+j] / B=w*x1[9+j]
// fold the path weights into per-j scalars; each (i,j) pair then costs
// u = fma(x2[i], B, x1[i]*A) per live output (2 ops instead of 3).
__device__ __forceinline__ void tp_cross(const float* __restrict__ x1,
                                         const float* __restrict__ x2,
                                         float* __restrict__ acc,
                                         float wA0, float wA1, float wB0, float wB1) {
    sfor<13>([&](auto J) {
        constexpr int j = decltype(J)::value;
        // per-j prescaled operands (transient registers)
        float A0 = wA0 * x2[9 + j];   // (4,6,4): x1[i] * A0
        float B0 = wB0 * x1[9 + j];   // (6,4,4): x2[i] * B0
        float A1 = wA1 * x2[9 + j];   // (4,6,6)
        float B1 = wB1 * x1[9 + j];   // (6,4,6)
        sfor<9>([&](auto I) {
            constexpr int i = decltype(I)::value;
            constexpr bool a0 = rowany(CG<4, 6, 4>, i, j, 9);
            constexpr bool b0 = rowany(CG<6, 4, 4>, j, i, 9);
            constexpr bool a1 = rowany(CG<4, 6, 6>, i, j, 13);
            constexpr bool b1 = rowany(CG<6, 4, 6>, j, i, 13);
            if constexpr (a0 || b0) {
                if constexpr (a0 && b0 && eqk(CG<4, 6, 4>, i, j, CG<6, 4, 4>, j, i, 9)) {
                    float u = __fmaf_rn(x2[i], B0, x1[i] * A0);
                    sfor<9>([&](auto K) {
                        constexpr int k = decltype(K)::value;
                        constexpr float cv = CG<4, 6, 4>.v[i][j][k];
                        if constexpr (cv != 0.0f) acc[k] = __fmaf_rn(cv, u, acc[k]);
                    });
                } else {
                    if constexpr (a0) {
                        float t1 = x1[i] * A0;
                        sfor<9>([&](auto K) {
                            constexpr int k = decltype(K)::value;
                            constexpr float cv = CG<4, 6, 4>.v[i][j][k];
                            if constexpr (cv != 0.0f) acc[k] = __fmaf_rn(cv, t1, acc[k]);
                        });
                    }
                    if constexpr (b0) {
                        float t2 = x2[i] * B0;
                        sfor<9>([&](auto K) {
                            constexpr int k = decltype(K)::value;
                            constexpr float cv = CG<6, 4, 4>.v[j][i][k];
                            if constexpr (cv != 0.0f) acc[k] = __fmaf_rn(cv, t2, acc[k]);
                        });
                    }
                }
            }
            if constexpr (a1 || b1) {
                if constexpr (a1 && b1 && eqk(CG<4, 6, 6>, i, j, CG<6, 4, 6>, j, i, 13)) {
                    float u = __fmaf_rn(x2[i], B1, x1[i] * A1);
                    sfor<13>([&](auto K) {
                        constexpr int k = decltype(K)::value;
                        constexpr float cv = CG<4, 6, 6>.v[i][j][k];
                        if constexpr (cv != 0.0f) acc[9 + k] = __fmaf_rn(cv, u, acc[9 + k]);
                    });
                } else {
                    if constexpr (a1) {
                        float t1 = x1[i] * A1;
                        sfor<13>([&](auto K) {
                            constexpr int k = decltype(K)::value;
                            constexpr float cv = CG<4, 6, 6>.v[i][j][k];
                            if constexpr (cv != 0.0f) acc[9 + k] = __fmaf_rn(cv, t1, acc[9 + k]);
                        });
                    }
                    if constexpr (b1) {
                        float t2 = x2[i] * B1;
                        sfor<13>([&](auto K) {
                            constexpr int k = decltype(K)::value;
                            constexpr float cv = CG<6, 4, 6>.v[j][i][k];
                            if constexpr (cv != 0.0f) acc[9 + k] = __fmaf_rn(cv, t2, acc[9 + k]);
                        });
                    }
                }
            }
        });
    });
}

// ---------------- kernel ----------------
constexpr int H = 768, W = 768;
constexpr int TX = 32, TY = 4;             // 128-thread tile
constexpr int NT = TX * TY;                // 128
constexpr int HTX = TX + 2, HTY = TY + 2;  // 34 x 6 haloed tile
constexpr int NPIX = HTX * HTY;            // 204
constexpr int RSTR = 23;                   // staging stride (coprime 32)

__global__ void __launch_bounds__(NT, 7) eq_spatial_tp_kernel(
    const float* __restrict__ f4, const float* __restrict__ f6,
    const float* __restrict__ sw, const float* __restrict__ wp,
    float* __restrict__ out4, float* __restrict__ out6) {
    // float4-group, pixel-major smem: groups 0-4 hold ch 4g..4g+3, group 5 ch 20-21.
    // After the TP this memory is dead and is re-used as the store staging
    // buffer (128 px x 23 floats = 11776 B < 17952 B).
    __shared__ float4 tile4[5][NPIX];   // 16320 B
    __shared__ float2 tile5[NPIX];      // 1632 B -> 17952 B total, 7 CTAs = 126 KB

    const int tid = threadIdx.x;
    const int bx = blockIdx.x, by = blockIdx.y;
    const int gx0 = bx * TX - 1, gy0 = by * TY - 1;

    // hoist weight loads so their latency overlaps the tile load
    float2 swp[9];
#pragma unroll
    for (int q = 0; q < 9; ++q) {
        float s = sw[q];
        swp[q] = make_float2(s, s);
    }
    float wcomb[8];
#pragma unroll
    for (int p = 0; p < 8; ++p) wcomb[p] = 0.5f * wp[p];  // ALPHA = 1/sqrt(4)

    // ---- pixel-outer haloed-tile load (2 pixels/thread, compile-time offsets) ----
#pragma unroll
    for (int pix = tid; pix < NPIX; pix += NT) {
        int r = pix / HTX, c = pix - r * HTX;
        int gy = gy0 + r; gy = gy < 0 ? 0 : (gy > H - 1 ? H - 1 : gy);
        int gx = gx0 + c; gx = gx < 0 ? 0 : (gx > W - 1 ? W - 1 : gx);
        int g = gy * W + gx;
        const float* p4 = f4 + g * 9;
        const float* p6 = f6 + g * 13;
        float v[22];
#pragma unroll
        for (int ch = 0; ch < 9; ++ch) v[ch] = p4[ch];
#pragma unroll
        for (int ch = 0; ch < 13; ++ch) v[9 + ch] = p6[ch];
#pragma unroll
        for (int gg = 0; gg < 5; ++gg)
            tile4[gg][pix] = make_float4(v[4 * gg], v[4 * gg + 1], v[4 * gg + 2], v[4 * gg + 3]);
        tile5[pix] = make_float2(v[20], v[21]);
    }
    __syncthreads();

    const int tx = tid & 31, ty = tid >> 5;

    // x1 = center features; x2 = weighted 3x3 neighbor average (packed f32x2)
    __align__(16) float x1[22];
    __align__(8) float x2[22];
    float2* x1v = reinterpret_cast<float2*>(x1);
    float2* x2v = reinterpret_cast<float2*>(x2);
    {
        const int cpix = (ty + 1) * HTX + (tx + 1);
#pragma unroll
        for (int gg = 0; gg < 5; ++gg) {
            float4 t = tile4[gg][cpix];
            x1v[2 * gg] = make_float2(t.x, t.y);
            x1v[2 * gg + 1] = make_float2(t.z, t.w);
        }
        x1v[10] = tile5[cpix];
#pragma unroll
        for (int p = 0; p < 11; ++p) x2v[p] = f2mul(swp[4], x1v[p]);
    }
#pragma unroll
    for (int dy = 0; dy < 3; ++dy)
#pragma unroll
        for (int dx = 0; dx < 3; ++dx) {
            if (dy == 1 && dx == 1) continue;
            const int npix = (ty + dy) * HTX + (tx + dx);
            const float2 wq = swp[dy * 3 + dx];
#pragma unroll
            for (int gg = 0; gg < 5; ++gg) {
                float4 t = tile4[gg][npix];
                x2v[2 * gg] = f2fma(wq, make_float2(t.x, t.y), x2v[2 * gg]);
                x2v[2 * gg + 1] = f2fma(wq, make_float2(t.z, t.w), x2v[2 * gg + 1]);
            }
            x2v[10] = f2fma(wq, tile5[npix], x2v[10]);
        }

    // ---- TP, ordered for register liveness ----
    float acc[22];
    {
        // diag44 unweighted -> z; acc born as x1 + w*z (z dies into acc)
        float z[22];
#pragma unroll
        for (int k = 0; k < 22; ++k) z[k] = 0.0f;
        tp_diag_z<4, 0>(x1, x2, z);
#pragma unroll
        for (int k = 0; k < 9; ++k) acc[k] = __fmaf_rn(wcomb[0], z[k], x1[k]);
#pragma unroll
        for (int k = 0; k < 13; ++k) acc[9 + k] = __fmaf_rn(wcomb[1], z[9 + k], x1[9 + k]);
    }

    // cross block (merged + j-prescaled), weighted into acc
    tp_cross(x1, x2, acc, wcomb[2], wcomb[3], wcomb[4], wcomb[5]);

    {
        // diag66 unweighted -> z (x1[0..8]/x2[0..8] dead by now)
        float z[22];
#pragma unroll
        for (int k = 0; k < 22; ++k) z[k] = 0.0f;
        tp_diag_z<6, 9>(x1, x2, z);
#pragma unroll
        for (int k = 0; k < 9; ++k) acc[k] = __fmaf_rn(wcomb[6], z[k], acc[k]);
#pragma unroll
        for (int k = 0; k < 13; ++k) acc[9 + k] = __fmaf_rn(wcomb[7], z[9 + k], acc[9 + k]);
    }

    // ---- staged coalesced stores ----
    // barrier: every thread's tile reads precede this point; after it the
    // tile smem is reused as the staging buffer.
    __syncthreads();
    float* resf = reinterpret_cast<float*>(tile4);
    {
        const int base = tid * RSTR;   // 23 coprime 32 -> conflict-free STS
#pragma unroll
        for (int k = 0; k < 22; ++k) resf[base + k] = acc[k];
    }
    __syncthreads();

    // out4 block region: 4 rows x 288 contiguous floats (16B-aligned bases)
    // out6 block region: 4 rows x 416 contiguous floats (16B-aligned bases)
    const int obase4 = (by * TY * W + bx * TX) * 9;
    const int obase6 = (by * TY * W + bx * TX) * 13;
    for (int e = tid; e < 288 + 416; e += NT) {
        if (e < 288) {
            int row = e / 72, q = e - row * 72;
            int fl = 4 * q;
            const int rb = row * (TX * RSTR);
            float4 vv;
            vv.x = resf[rb + ((fl + 0) / 9) * RSTR + (fl + 0) % 9];
            vv.y = resf[rb + ((fl + 1) / 9) * RSTR + (fl + 1) % 9];
            vv.z = resf[rb + ((fl + 2) / 9) * RSTR + (fl + 2) % 9];
            vv.w = resf[rb + ((fl + 3) / 9) * RSTR + (fl + 3) % 9];
            *reinterpret_cast<float4*>(out4 + obase4 + row * (W * 9) + fl) = vv;
        } else {
            int e2 = e - 288;
            int row = e2 / 104, q = e2 - row * 104;
            int fl = 4 * q;
            const int rb = row * (TX * RSTR);
            float4 vv;
            vv.x = resf[rb + ((fl + 0) / 13) * RSTR + 9 + (fl + 0) % 13];
            vv.y = resf[rb + ((fl + 1) / 13) * RSTR + 9 + (fl + 1) % 13];
            vv.z = resf[rb + ((fl + 2) / 13) * RSTR + 9 + (fl + 2) % 13];
            vv.w = resf[rb + ((fl + 3) / 13) * RSTR + 9 + (fl + 3) % 13];
            *reinterpret_cast<float4*>(out6 + obase6 + row * (W * 13) + fl) = vv;
        }
    }
}

extern "C" void kernel_launch(void* const* d_in, const int* in_sizes, int n_in,
                              void* d_out, int out_size) {
    const float* f4 = (const float*)d_in[0];
    const float* f6 = (const float*)d_in[1];
    const float* sw = (const float*)d_in[2];  // spatial_weights [3,3]
    const float* wp = (const float*)d_in[3];  // w_paths [8]
    float* out = (float*)d_out;
    const size_t N = (size_t)H * W;

    dim3 grid(W / TX, H / TY);  // 24 x 192
    eq_spatial_tp_kernel<<<grid, NT>>>(f4, f6, sw, wp, out, out + N * 9);
}

// round 16
// speedup vs baseline: 1.2491x; 1.0031x over previous
#include <cuda_runtime.h>

// ============================================================================
// EquivariantSpatialConv: fused 3x3 replicate-pad depthwise spatial average
// + fully-connected CG tensor product (irreps 1x4e + 1x6e) + residual.
//
// R16 (= R15 fixed): LUT-driven staged stores; the LUT build now covers ALL
// 176 entries via a strided loop (R15 only wrote 56/104 of slut6s with its
// tid-range predicate -> garbage offsets -> illegal access). Store hot loop
// has zero runtime divmods. Arithmetic bit-identical to R13/R14.
// ============================================================================

#define DEVHOST __host__ __device__

// ---------------- compile-time scalar math ----------------
DEVHOST constexpr double cfact(int n) {
    double r = 1.0;
    for (int i = 2; i <= n; ++i) r *= (double)i;
    return r;
}

DEVHOST constexpr double csqrt(double x) {
    if (x <= 0.0) return 0.0;
    double g = x > 1.0 ? x : 1.0;
    for (int it = 0; it < 48; ++it) g = 0.5 * (g + x / g);
    return g;
}

struct CD { double re, im; };
DEVHOST constexpr CD cmul(CD a, CD b) {
    return CD{a.re * b.re - a.im * b.im, a.re * b.im + a.im * b.re};
}
DEVHOST constexpr CD cconj(CD a) { return CD{a.re, -a.im}; }

DEVHOST constexpr double su2_cg(int j1, int j2, int j3, int m1, int m2, int m3) {
    if (m3 != m1 + m2) return 0.0;
    if (m1 < -j1 || m1 > j1 || m2 < -j2 || m2 > j2 || m3 < -j3 || m3 > j3) return 0.0;
    double pref0 = (2.0 * j3 + 1.0) * cfact(j1 + j2 - j3) * cfact(j1 - j2 + j3) *
                   cfact(-j1 + j2 + j3) / cfact(j1 + j2 + j3 + 1);
    double pref = csqrt(pref0 * cfact(j3 + m3) * cfact(j3 - m3) * cfact(j1 - m1) *
                        cfact(j1 + m1) * cfact(j2 - m2) * cfact(j2 + m2));
    int kmin = 0;
    if (-(j3 - j2 + m1) > kmin) kmin = -(j3 - j2 + m1);
    if (-(j3 - j1 - m2) > kmin) kmin = -(j3 - j1 - m2);
    int kmax = j1 + j2 - j3;
    if (j1 - m1 < kmax) kmax = j1 - m1;
    if (j2 + m2 < kmax) kmax = j2 + m2;
    double s = 0.0;
    for (int k = kmin; k <= kmax; ++k) {
        double d = cfact(k) * cfact(j1 + j2 - j3 - k) * cfact(j1 - m1 - k) *
                   cfact(j2 + m2 - k) * cfact(j3 - j2 + m1 + k) * cfact(j3 - j1 - m2 + k);
        s += ((k & 1) ? -1.0 : 1.0) / d;
    }
    return pref * s;
}

DEVHOST constexpr CD qent(int l, int r, int c) {
    constexpr double S2 = 0.70710678118654752440;
    int m = r - l;
    CD v{0.0, 0.0};
    if (m < 0) {
        if (c == l - m)      v = CD{S2, 0.0};
        else if (c == l + m) v = CD{0.0, -S2};
    } else if (m == 0) {
        if (c == l) v = CD{1.0, 0.0};
    } else {
        double sg = (m & 1) ? -1.0 : 1.0;
        if (c == l + m)      v = CD{sg * S2, 0.0};
        else if (c == l - m) v = CD{0.0, sg * S2};
    }
    int ph = l & 3;
    CD f = (ph == 0) ? CD{1, 0} : (ph == 1) ? CD{0, -1} : (ph == 2) ? CD{-1, 0} : CD{0, 1};
    return cmul(v, f);
}

DEVHOST constexpr double real_cg_entry(int l1, int l2, int l3, int a, int b, int c) {
    int d1 = a >= l1 ? a - l1 : l1 - a;
    int d2 = b >= l2 ? b - l2 : l2 - b;
    int d3 = c >= l3 ? c - l3 : l3 - c;
    CD sum{0.0, 0.0};
    int ni = d1 ? 2 : 1;
    int nk = d2 ? 2 : 1;
    for (int si = 0; si < ni; ++si) {
        int i = d1 ? (si ? l1 + d1 : l1 - d1) : l1;
        int m1 = i - l1;
        CD q1 = qent(l1, i, a);
        for (int sk = 0; sk < nk; ++sk) {
            int k = d2 ? (sk ? l2 + d2 : l2 - d2) : l2;
            int m2 = k - l2;
            int m3 = m1 + m2;
            if (m3 < -l3 || m3 > l3) continue;
            int am3 = m3 < 0 ? -m3 : m3;
            if (am3 != d3) continue;
            int n = l3 + m3;
            CD q2 = qent(l2, k, b);
            CD q3 = cconj(qent(l3, c, n));
            double C = su2_cg(l1, l2, l3, m1, m2, m3);
            CD t = cmul(cmul(q1, q2), q3);
            sum.re += t.re * C;
            sum.im += t.im * C;
        }
    }
    return sum.re;
}

template <int L1, int L2, int L3>
struct CGT {
    float v[2 * L1 + 1][2 * L2 + 1][2 * L3 + 1];
};

template <int L1, int L2, int L3>
DEVHOST constexpr CGT<L1, L2, L3> make_cg() {
    double tmp[2 * L1 + 1][2 * L2 + 1][2 * L3 + 1] = {};
    double ss = 0.0;
    for (int a = 0; a < 2 * L1 + 1; ++a)
        for (int b = 0; b < 2 * L2 + 1; ++b)
            for (int c = 0; c < 2 * L3 + 1; ++c) {
                double e = real_cg_entry(L1, L2, L3, a, b, c);
                tmp[a][b][c] = e;
                ss += e * e;
            }
    double inv = 1.0 / csqrt(ss);
    CGT<L1, L2, L3> r{};
    for (int a = 0; a < 2 * L1 + 1; ++a)
        for (int b = 0; b < 2 * L2 + 1; ++b)
            for (int c = 0; c < 2 * L3 + 1; ++c)
                r.v[a][b][c] = (float)(tmp[a][b][c] * inv);
    return r;
}

// Namespace-scope constexpr CG tensors (static storage: usable in constant
// expressions from any lambda depth inside function templates).
template <int L1, int L2, int L3>
inline constexpr CGT<L1, L2, L3> CG = make_cg<L1, L2, L3>();

// ---------------- compile-time unrolling helpers ----------------
template <int V> struct IC { static constexpr int value = V; };

template <int N, int I = 0, class F>
__device__ __forceinline__ void sfor(F&& f) {
    if constexpr (I < N) {
        f(IC<I>{});
        sfor<N, I + 1>(static_cast<F&&>(f));
    }
}

template <class T>
DEVHOST constexpr bool rowany(const T& t, int a, int b, int dk) {
    for (int k = 0; k < dk; ++k)
        if (t.v[a][b][k] != 0.0f) return true;
    return false;
}
template <class T>
DEVHOST constexpr bool rowany2(const T& t, int a, int b, int dk) {
    for (int k = 0; k < dk; ++k)
        if (t.v[a][b][k] != 0.0f || t.v[b][a][k] != 0.0f) return true;
    return false;
}
template <class T>
DEVHOST constexpr bool symk(const T& t, int a, int b, int dk) {
    for (int k = 0; k < dk; ++k)
        if (t.v[a][b][k] != t.v[b][a][k]) return false;
    return true;
}
template <class TA, class TB>
DEVHOST constexpr bool eqk(const TA& A, int i, int j, const TB& B, int bi, int bj, int dk) {
    for (int k = 0; k < dk; ++k)
        if (A.v[i][j][k] != B.v[bi][bj][k]) return false;
    return true;
}

// ---------------- packed f32x2 helpers ----------------
__device__ __forceinline__ float2 f2fma(float2 a, float2 b, float2 c) {
    float2 d;
    asm("fma.rn.f32x2 %0, %1, %2, %3;"
        : "=l"(*reinterpret_cast<unsigned long long*>(&d))
        : "l"(*reinterpret_cast<unsigned long long*>(&a)),
          "l"(*reinterpret_cast<unsigned long long*>(&b)),
          "l"(*reinterpret_cast<unsigned long long*>(&c)));
    return d;
}
__device__ __forceinline__ float2 f2mul(float2 a, float2 b) {
    float2 d;
    asm("mul.rn.f32x2 %0, %1, %2;"
        : "=l"(*reinterpret_cast<unsigned long long*>(&d))
        : "l"(*reinterpret_cast<unsigned long long*>(&a)),
          "l"(*reinterpret_cast<unsigned long long*>(&b)));
    return d;
}

// ---------------- tensor-product blocks ----------------
// Diagonal block (L,L,*): UNWEIGHTED accumulation into z[22]
// (z[0..8] <- CG<L,L,4>, z[9..21] <- CG<L,L,6>); weights applied by caller.
template <int L, int O>
__device__ __forceinline__ void tp_diag_z(const float* __restrict__ x1,
                                          const float* __restrict__ x2,
                                          float* __restrict__ z) {
    constexpr int D = 2 * L + 1;
    sfor<D>([&](auto I) {
        constexpr int i = decltype(I)::value;
        sfor<D>([&](auto J) {
            constexpr int j = decltype(J)::value;
            if constexpr (j >= i) {
                constexpr bool l0 = rowany2(CG<L, L, 4>, i, j, 9);
                constexpr bool l1 = rowany2(CG<L, L, 6>, i, j, 13);
                if constexpr (l0 || l1) {
                    if constexpr (i == j) {
                        float p = x1[O + i] * x2[O + i];
                        sfor<9>([&](auto K) {
                            constexpr int k = decltype(K)::value;
                            constexpr float cv = CG<L, L, 4>.v[i][i][k];
                            if constexpr (cv != 0.0f) z[k] = __fmaf_rn(cv, p, z[k]);
                        });
                        sfor<13>([&](auto K) {
                            constexpr int k = decltype(K)::value;
                            constexpr float cv = CG<L, L, 6>.v[i][i][k];
                            if constexpr (cv != 0.0f) z[9 + k] = __fmaf_rn(cv, p, z[9 + k]);
                        });
                    } else if constexpr (symk(CG<L, L, 4>, i, j, 9) && symk(CG<L, L, 6>, i, j, 13)) {
                        float s = __fmaf_rn(x1[O + j], x2[O + i], x1[O + i] * x2[O + j]);
                        sfor<9>([&](auto K) {
                            constexpr int k = decltype(K)::value;
                            constexpr float cv = CG<L, L, 4>.v[i][j][k];
                            if constexpr (cv != 0.0f) z[k] = __fmaf_rn(cv, s, z[k]);
                        });
                        sfor<13>([&](auto K) {
                            constexpr int k = decltype(K)::value;
                            constexpr float cv = CG<L, L, 6>.v[i][j][k];
                            if constexpr (cv != 0.0f) z[9 + k] = __fmaf_rn(cv, s, z[9 + k]);
                        });
                    } else {
                        // fallback (not expected for even l1+l2+l3): both orders
                        float p1 = x1[O + i] * x2[O + j];
                        float p2 = x1[O + j] * x2[O + i];
                        sfor<9>([&](auto K) {
                            constexpr int k = decltype(K)::value;
                            constexpr float c1 = CG<L, L, 4>.v[i][j][k];
                            constexpr float c2 = CG<L, L, 4>.v[j][i][k];
                            if constexpr (c1 != 0.0f) z[k] = __fmaf_rn(c1, p1, z[k]);
                            if constexpr (c2 != 0.0f) z[k] = __fmaf_rn(c2, p2, z[k]);
                        });
                        sfor<13>([&](auto K) {
                            constexpr int k = decltype(K)::value;
                            constexpr float c1 = CG<L, L, 6>.v[i][j][k];
                            constexpr float c2 = CG<L, L, 6>.v[j][i][k];
                            if constexpr (c1 != 0.0f) z[9 + k] = __fmaf_rn(c1, p1, z[9 + k]);
                            if constexpr (c2 != 0.0f) z[9 + k] = __fmaf_rn(c2, p2, z[9 + k]);
                        });
                    }
                }
            }
        });
    });
}

// Cross block with j-outer prescaling: for each j, A=w*x2[9+j] / B=w*x1[9+j]
// fold the path weights into per-j scalars; each (i,j) pair then costs
// u = fma(x2[i], B, x1[i]*A) per live output (2 ops instead of 3).
__device__ __forceinline__ void tp_cross(const float* __restrict__ x1,
                                         const float* __restrict__ x2,
                                         float* __restrict__ acc,
                                         float wA0, float wA1, float wB0, float wB1) {
    sfor<13>([&](auto J) {
        constexpr int j = decltype(J)::value;
        // per-j prescaled operands (transient registers)
        float A0 = wA0 * x2[9 + j];   // (4,6,4): x1[i] * A0
        float B0 = wB0 * x1[9 + j];   // (6,4,4): x2[i] * B0
        float A1 = wA1 * x2[9 + j];   // (4,6,6)
        float B1 = wB1 * x1[9 + j];   // (6,4,6)
        sfor<9>([&](auto I) {
            constexpr int i = decltype(I)::value;
            constexpr bool a0 = rowany(CG<4, 6, 4>, i, j, 9);
            constexpr bool b0 = rowany(CG<6, 4, 4>, j, i, 9);
            constexpr bool a1 = rowany(CG<4, 6, 6>, i, j, 13);
            constexpr bool b1 = rowany(CG<6, 4, 6>, j, i, 13);
            if constexpr (a0 || b0) {
                if constexpr (a0 && b0 && eqk(CG<4, 6, 4>, i, j, CG<6, 4, 4>, j, i, 9)) {
                    float u = __fmaf_rn(x2[i], B0, x1[i] * A0);
                    sfor<9>([&](auto K) {
                        constexpr int k = decltype(K)::value;
                        constexpr float cv = CG<4, 6, 4>.v[i][j][k];
                        if constexpr (cv != 0.0f) acc[k] = __fmaf_rn(cv, u, acc[k]);
                    });
                } else {
                    if constexpr (a0) {
                        float t1 = x1[i] * A0;
                        sfor<9>([&](auto K) {
                            constexpr int k = decltype(K)::value;
                            constexpr float cv = CG<4, 6, 4>.v[i][j][k];
                            if constexpr (cv != 0.0f) acc[k] = __fmaf_rn(cv, t1, acc[k]);
                        });
                    }
                    if constexpr (b0) {
                        float t2 = x2[i] * B0;
                        sfor<9>([&](auto K) {
                            constexpr int k = decltype(K)::value;
                            constexpr float cv = CG<6, 4, 4>.v[j][i][k];
                            if constexpr (cv != 0.0f) acc[k] = __fmaf_rn(cv, t2, acc[k]);
                        });
                    }
                }
            }
            if constexpr (a1 || b1) {
                if constexpr (a1 && b1 && eqk(CG<4, 6, 6>, i, j, CG<6, 4, 6>, j, i, 13)) {
                    float u = __fmaf_rn(x2[i], B1, x1[i] * A1);
                    sfor<13>([&](auto K) {
                        constexpr int k = decltype(K)::value;
                        constexpr float cv = CG<4, 6, 6>.v[i][j][k];
                        if constexpr (cv != 0.0f) acc[9 + k] = __fmaf_rn(cv, u, acc[9 + k]);
                    });
                } else {
                    if constexpr (a1) {
                        float t1 = x1[i] * A1;
                        sfor<13>([&](auto K) {
                            constexpr int k = decltype(K)::value;
                            constexpr float cv = CG<4, 6, 6>.v[i][j][k];
                            if constexpr (cv != 0.0f) acc[9 + k] = __fmaf_rn(cv, t1, acc[9 + k]);
                        });
                    }
                    if constexpr (b1) {
                        float t2 = x2[i] * B1;
                        sfor<13>([&](auto K) {
                            constexpr int k = decltype(K)::value;
                            constexpr float cv = CG<6, 4, 6>.v[j][i][k];
                            if constexpr (cv != 0.0f) acc[9 + k] = __fmaf_rn(cv, t2, acc[9 + k]);
                        });
                    }
                }
            }
        });
    });
}

// ---------------- kernel ----------------
constexpr int H = 768, W = 768;
constexpr int TX = 32, TY = 4;             // 128-thread tile
constexpr int NT = TX * TY;                // 128
constexpr int HTX = TX + 2, HTY = TY + 2;  // 34 x 6 haloed tile
constexpr int NPIX = HTX * HTY;            // 204
constexpr int RSTR = 23;                   // staging stride (coprime 32)

__global__ void __launch_bounds__(NT, 7) eq_spatial_tp_kernel(
    const float* __restrict__ f4, const float* __restrict__ f6,
    const float* __restrict__ sw, const float* __restrict__ wp,
    float* __restrict__ out4, float* __restrict__ out6) {
    // float4-group, pixel-major smem: groups 0-4 hold ch 4g..4g+3, group 5 ch 20-21.
    // After the TP this memory is dead and is re-used as the store staging
    // buffer (128 px x 23 floats = 11776 B < 17952 B).
    __shared__ float4 tile4[5][NPIX];   // 16320 B
    __shared__ float2 tile5[NPIX];      // 1632 B
    // scatter-offset LUTs for the staged store (built once, before barrier)
    __shared__ int4 slut4s[72];         // out4: per-row float4 q -> 4 staging offsets
    __shared__ int4 slut6s[104];        // out6

    const int tid = threadIdx.x;
    const int bx = blockIdx.x, by = blockIdx.y;
    const int gx0 = bx * TX - 1, gy0 = by * TY - 1;

    // hoist weight loads so their latency overlaps the tile load
    float2 swp[9];
#pragma unroll
    for (int q = 0; q < 9; ++q) {
        float s = sw[q];
        swp[q] = make_float2(s, s);
    }
    float wcomb[8];
#pragma unroll
    for (int p = 0; p < 8; ++p) wcomb[p] = 0.5f * wp[p];  // ALPHA = 1/sqrt(4)

    // ---- build store LUTs: ALL 176 entries (strided; divmods once per CTA) ----
    for (int t = tid; t < 72 + 104; t += NT) {
        if (t < 72) {
            int fl = 4 * t;
            slut4s[t] = make_int4(((fl + 0) / 9) * RSTR + (fl + 0) % 9,
                                  ((fl + 1) / 9) * RSTR + (fl + 1) % 9,
                                  ((fl + 2) / 9) * RSTR + (fl + 2) % 9,
                                  ((fl + 3) / 9) * RSTR + (fl + 3) % 9);
        } else {
            int q = t - 72;
            int fl = 4 * q;
            slut6s[q] = make_int4(((fl + 0) / 13) * RSTR + 9 + (fl + 0) % 13,
                                  ((fl + 1) / 13) * RSTR + 9 + (fl + 1) % 13,
                                  ((fl + 2) / 13) * RSTR + 9 + (fl + 2) % 13,
                                  ((fl + 3) / 13) * RSTR + 9 + (fl + 3) % 13);
        }
    }

    // ---- pixel-outer haloed-tile load (2 pixels/thread, compile-time offsets) ----
#pragma unroll
    for (int pix = tid; pix < NPIX; pix += NT) {
        int r = pix / HTX, c = pix - r * HTX;
        int gy = gy0 + r; gy = gy < 0 ? 0 : (gy > H - 1 ? H - 1 : gy);
        int gx = gx0 + c; gx = gx < 0 ? 0 : (gx > W - 1 ? W - 1 : gx);
        int g = gy * W + gx;
        const float* p4 = f4 + g * 9;
        const float* p6 = f6 + g * 13;
        float v[22];
#pragma unroll
        for (int ch = 0; ch < 9; ++ch) v[ch] = p4[ch];
#pragma unroll
        for (int ch = 0; ch < 13; ++ch) v[9 + ch] = p6[ch];
#pragma unroll
        for (int gg = 0; gg < 5; ++gg)
            tile4[gg][pix] = make_float4(v[4 * gg], v[4 * gg + 1], v[4 * gg + 2], v[4 * gg + 3]);
        tile5[pix] = make_float2(v[20], v[21]);
    }
    __syncthreads();

    const int tx = tid & 31, ty = tid >> 5;

    // x1 = center features; x2 = weighted 3x3 neighbor average (packed f32x2)
    __align__(16) float x1[22];
    __align__(8) float x2[22];
    float2* x1v = reinterpret_cast<float2*>(x1);
    float2* x2v = reinterpret_cast<float2*>(x2);
    {
        const int cpix = (ty + 1) * HTX + (tx + 1);
#pragma unroll
        for (int gg = 0; gg < 5; ++gg) {
            float4 t = tile4[gg][cpix];
            x1v[2 * gg] = make_float2(t.x, t.y);
            x1v[2 * gg + 1] = make_float2(t.z, t.w);
        }
        x1v[10] = tile5[cpix];
#pragma unroll
        for (int p = 0; p < 11; ++p) x2v[p] = f2mul(swp[4], x1v[p]);
    }
#pragma unroll
    for (int dy = 0; dy < 3; ++dy)
#pragma unroll
        for (int dx = 0; dx < 3; ++dx) {
            if (dy == 1 && dx == 1) continue;
            const int npix = (ty + dy) * HTX + (tx + dx);
            const float2 wq = swp[dy * 3 + dx];
#pragma unroll
            for (int gg = 0; gg < 5; ++gg) {
                float4 t = tile4[gg][npix];
                x2v[2 * gg] = f2fma(wq, make_float2(t.x, t.y), x2v[2 * gg]);
                x2v[2 * gg + 1] = f2fma(wq, make_float2(t.z, t.w), x2v[2 * gg + 1]);
            }
            x2v[10] = f2fma(wq, tile5[npix], x2v[10]);
        }

    // ---- TP, ordered for register liveness ----
    float acc[22];
    {
        // diag44 unweighted -> z; acc born as x1 + w*z (z dies into acc)
        float z[22];
#pragma unroll
        for (int k = 0; k < 22; ++k) z[k] = 0.0f;
        tp_diag_z<4, 0>(x1, x2, z);
#pragma unroll
        for (int k = 0; k < 9; ++k) acc[k] = __fmaf_rn(wcomb[0], z[k], x1[k]);
#pragma unroll
        for (int k = 0; k < 13; ++k) acc[9 + k] = __fmaf_rn(wcomb[1], z[9 + k], x1[9 + k]);
    }

    // cross block (merged + j-prescaled), weighted into acc
    tp_cross(x1, x2, acc, wcomb[2], wcomb[3], wcomb[4], wcomb[5]);

    {
        // diag66 unweighted -> z (x1[0..8]/x2[0..8] dead by now)
        float z[22];
#pragma unroll
        for (int k = 0; k < 22; ++k) z[k] = 0.0f;
        tp_diag_z<6, 9>(x1, x2, z);
#pragma unroll
        for (int k = 0; k < 9; ++k) acc[k] = __fmaf_rn(wcomb[6], z[k], acc[k]);
#pragma unroll
        for (int k = 0; k < 13; ++k) acc[9 + k] = __fmaf_rn(wcomb[7], z[9 + k], acc[9 + k]);
    }

    // ---- staged coalesced stores (LUT-driven, no hot-loop divmods) ----
    __syncthreads();   // all tile reads done; smem becomes the staging buffer
    float* resf = reinterpret_cast<float*>(tile4);
    {
        const int base = tid * RSTR;   // 23 coprime 32 -> conflict-free STS
#pragma unroll
        for (int k = 0; k < 22; ++k) resf[base + k] = acc[k];
    }
    __syncthreads();

    // per row: 72 out4-float4s + 104 out6-float4s = 176 units; 4 rows unrolled
    const int obase4 = (by * TY * W + bx * TX) * 9;
    const int obase6 = (by * TY * W + bx * TX) * 13;
#pragma unroll
    for (int row = 0; row < TY; ++row) {
        const int rb = row * (TX * RSTR);            // compile-time * row
        float* o4 = out4 + obase4 + row * (W * 9);   // row bases folded
        float* o6 = out6 + obase6 + row * (W * 13);
        for (int u = tid; u < 176; u += NT) {
            if (u < 72) {
                int4 s = slut4s[u];
                float4 vv = make_float4(resf[rb + s.x], resf[rb + s.y],
                                        resf[rb + s.z], resf[rb + s.w]);
                *reinterpret_cast<float4*>(o4 + 4 * u) = vv;
            } else {
                int q = u - 72;
                int4 s = slut6s[q];
                float4 vv = make_float4(resf[rb + s.x], resf[rb + s.y],
                                        resf[rb + s.z], resf[rb + s.w]);
                *reinterpret_cast<float4*>(o6 + 4 * q) = vv;
            }
        }
    }
}

extern "C" void kernel_launch(void* const* d_in, const int* in_sizes, int n_in,
                              void* d_out, int out_size) {
    const float* f4 = (const float*)d_in[0];
    const float* f6 = (const float*)d_in[1];
    const float* sw = (const float*)d_in[2];  // spatial_weights [3,3]
    const float* wp = (const float*)d_in[3];  // w_paths [8]
    float* out = (float*)d_out;
    const size_t N = (size_t)H * W;

    dim3 grid(W / TX, H / TY);  // 24 x 192
    eq_spatial_tp_kernel<<<grid, NT>>>(f4, f6, sw, wp, out, out + N * 9);
}